// round 6
// baseline (speedup 1.0000x reference)
#include <cuda_runtime.h>
#include <cuda_bf16.h>
#include <cstdint>

#define NN 30000          // nodes per graph
#define DD 768            // feature dim
#define NE 480000         // edges per graph
#define K2 (2*DD)         // GEMM K = 1536

// ---------------- scratch (static device memory; no allocs) ----------------
__device__ unsigned short g_ah[(size_t)NN * DD];   // bf16 hi of agg (pre-scaled)
__device__ unsigned short g_al[(size_t)NN * DD];   // bf16 lo
__device__ unsigned short g_xh[(size_t)NN * DD];   // bf16 hi of x
__device__ unsigned short g_xl[(size_t)NN * DD];
__device__ unsigned short g_bh[(size_t)DD * K2];   // bf16 hi of [Wl1|Wr1], row j, col k
__device__ unsigned short g_bl[(size_t)DD * K2];
__device__ int   g_cnt[NN];
__device__ float g_inv[NN];
__device__ float g_cw[NN];                         // c_j = sum over out-edges of inv[dst]
__device__ int   g_start[NN + 1];
__device__ int   g_cursor[NN];
__device__ int   g_sorted[NE];
__device__ float g_colsum[DD];                     // sum over nodes of h
__device__ float g_s2[DD];                         // sum_j c_j h_j = N*mean(agg2)
__device__ float g_agg2var[DD];
__device__ float g_rowvar[DD];
__device__ float g_emb1[DD], g_emb2[DD], g_embt[DD];
__device__ float g_feats[3 * DD];
__device__ float g_outv[DD], g_tgt[DD];

// ---------------- helpers ----------------
__device__ __forceinline__ unsigned short bfh(float v) {
    __nv_bfloat16 h = __float2bfloat16(v);
    return *reinterpret_cast<unsigned short*>(&h);
}
__device__ __forceinline__ float bf2f(unsigned short u) {
    __nv_bfloat16 h = *reinterpret_cast<__nv_bfloat16*>(&u);
    return __bfloat162float(h);
}
__device__ __forceinline__ void cpa16(uint32_t d, const void* s, int sz) {
    asm volatile("cp.async.cg.shared.global [%0], [%1], 16, %2;"
                 :: "r"(d), "l"(s), "r"(sz) : "memory");
}
#define CP_COMMIT() asm volatile("cp.async.commit_group;" ::: "memory")
#define CP_WAIT1()  asm volatile("cp.async.wait_group 1;" ::: "memory")

#define MMA_BF16(acc, a0, a1, a2, a3, b0, b1) \
    asm volatile("mma.sync.aligned.m16n8k16.row.col.f32.bf16.bf16.f32 " \
        "{%0,%1,%2,%3}, {%4,%5,%6,%7}, {%8,%9}, {%0,%1,%2,%3};" \
        : "+f"((acc)[0]), "+f"((acc)[1]), "+f"((acc)[2]), "+f"((acc)[3]) \
        : "r"(a0), "r"(a1), "r"(a2), "r"(a3), "r"(b0), "r"(b1))

// ---------------- graph prep ----------------
__global__ void zero_graph_kernel() {
    int t = blockIdx.x * 256 + threadIdx.x;
    if (t < NN) { g_cnt[t] = 0; g_cw[t] = 0.f; }
    if (t < DD) { g_colsum[t] = 0.f; g_s2[t] = 0.f; g_agg2var[t] = 0.f; }
}

__global__ void count_kernel(const int* __restrict__ ei) {
    int e = blockIdx.x * 256 + threadIdx.x;
    if (e < NE) atomicAdd(&g_cnt[ei[NE + e]], 1);
}

// warp-region scan: 32 warps, each owns a contiguous coalesced region.
#define REG_SZ 938   // ceil(30000/32)
__global__ void prefix_kernel() {
    int tid = threadIdx.x;
    int lane = tid & 31, w = tid >> 5;
    int r0 = w * REG_SZ;
    int r1 = min(r0 + REG_SZ, NN);

    // pass 1: region sums (coalesced lane-strided)
    int s = 0;
    for (int idx = r0 + lane; idx < r1; idx += 32) s += g_cnt[idx];
    #pragma unroll
    for (int o = 16; o; o >>= 1) s += __shfl_xor_sync(0xffffffffu, s, o);

    __shared__ int woff[32];
    if (lane == 0) woff[w] = s;
    __syncthreads();
    if (w == 0) {
        int v = woff[lane];
        int iv = v;
        #pragma unroll
        for (int o = 1; o < 32; o <<= 1) {
            int u = __shfl_up_sync(0xffffffffu, iv, o);
            if (lane >= o) iv += u;
        }
        woff[lane] = iv - v;   // exclusive
    }
    __syncthreads();

    // pass 2: per-region running scan, 32-wide tiles, no block syncs
    int running = woff[w];
    for (int base = r0; base < r1; base += 32) {
        int idx = base + lane;
        int v = (idx < r1) ? g_cnt[idx] : 0;
        int incl = v;
        #pragma unroll
        for (int o = 1; o < 32; o <<= 1) {
            int u = __shfl_up_sync(0xffffffffu, incl, o);
            if (lane >= o) incl += u;
        }
        if (idx < r1) {
            int excl = running + incl - v;
            g_start[idx] = excl;
            g_cursor[idx] = excl;
            g_inv[idx] = 1.0f / (float)max(v, 1);
        }
        running += __shfl_sync(0xffffffffu, incl, 31);
    }
    if (w == 31 && lane == 0) g_start[NN] = running;
}

// placement + c-weight scatter fused
__global__ void place_kernel(const int* __restrict__ ei) {
    int e = blockIdx.x * 256 + threadIdx.x;
    if (e < NE) {
        int s = ei[e], t = ei[NE + e];
        int pos = atomicAdd(&g_cursor[t], 1);
        g_sorted[pos] = s;
        atomicAdd(&g_cw[s], g_inv[t]);
    }
}

// ---------------- weight / x splits ----------------
__global__ void convert_b_kernel(const float* __restrict__ Wl, const float* __restrict__ Wr) {
    int i = blockIdx.x * 256 + threadIdx.x;
    if (i < DD * K2) {
        int j = i / K2, k = i % K2;
        float v = (k < DD) ? Wl[(size_t)j * DD + k] : Wr[(size_t)j * DD + (k - DD)];
        unsigned short hi = bfh(v);
        g_bh[i] = hi;
        g_bl[i] = bfh(v - bf2f(hi));
    }
}

__global__ void convert_x_kernel(const float* __restrict__ x) {
    size_t i = ((size_t)blockIdx.x * 256 + threadIdx.x) * 8;
    if (i >= (size_t)NN * DD) return;
    float4 v0 = *(const float4*)(x + i);
    float4 v1 = *(const float4*)(x + i + 4);
    float vv[8] = {v0.x, v0.y, v0.z, v0.w, v1.x, v1.y, v1.z, v1.w};
    unsigned short h[8], l[8];
    #pragma unroll
    for (int j = 0; j < 8; j++) {
        h[j] = bfh(vv[j]);
        l[j] = bfh(vv[j] - bf2f(h[j]));
    }
    uint4 H, L;
    H.x = h[0] | ((uint32_t)h[1] << 16); H.y = h[2] | ((uint32_t)h[3] << 16);
    H.z = h[4] | ((uint32_t)h[5] << 16); H.w = h[6] | ((uint32_t)h[7] << 16);
    L.x = l[0] | ((uint32_t)l[1] << 16); L.y = l[2] | ((uint32_t)l[3] << 16);
    L.z = l[4] | ((uint32_t)l[5] << 16); L.w = l[6] | ((uint32_t)l[7] << 16);
    *(uint4*)(g_xh + i) = H;
    *(uint4*)(g_xl + i) = L;
}

// ---------------- layer-1 aggregation: gather by dst segment -> bf16 hi/lo --
__global__ void gather_agg_kernel(const float* __restrict__ x) {
    int warp = threadIdx.x >> 5, lane = threadIdx.x & 31;
    int node = blockIdx.x * 8 + warp;
    int d = blockIdx.y * 128 + lane * 4;
    int p0 = g_start[node], p1 = g_start[node + 1];
    float4 acc = make_float4(0.f, 0.f, 0.f, 0.f);
    int p = p0;
    for (; p + 4 <= p1; p += 4) {
        int s0 = g_sorted[p], s1 = g_sorted[p+1], s2 = g_sorted[p+2], s3 = g_sorted[p+3];
        float4 v0 = *(const float4*)(x + (size_t)s0 * DD + d);
        float4 v1 = *(const float4*)(x + (size_t)s1 * DD + d);
        float4 v2 = *(const float4*)(x + (size_t)s2 * DD + d);
        float4 v3 = *(const float4*)(x + (size_t)s3 * DD + d);
        acc.x += v0.x + v1.x + v2.x + v3.x;
        acc.y += v0.y + v1.y + v2.y + v3.y;
        acc.z += v0.z + v1.z + v2.z + v3.z;
        acc.w += v0.w + v1.w + v2.w + v3.w;
    }
    for (; p < p1; p++) {
        int s = g_sorted[p];
        float4 v = *(const float4*)(x + (size_t)s * DD + d);
        acc.x += v.x; acc.y += v.y; acc.z += v.z; acc.w += v.w;
    }
    float inv = g_inv[node];
    acc.x *= inv; acc.y *= inv; acc.z *= inv; acc.w *= inv;
    ushort4 hv, lv;
    hv.x = bfh(acc.x); lv.x = bfh(acc.x - bf2f(hv.x));
    hv.y = bfh(acc.y); lv.y = bfh(acc.y - bf2f(hv.y));
    hv.z = bfh(acc.z); lv.z = bfh(acc.z - bf2f(hv.z));
    hv.w = bfh(acc.w); lv.w = bfh(acc.w - bf2f(hv.w));
    *(ushort4*)(g_ah + (size_t)node * DD + d) = hv;
    *(ushort4*)(g_al + (size_t)node * DD + d) = lv;
}

// ---------------- bf16 3-split mma.sync GEMM, cp.async 3-stage pipeline -----
// grid (6 n-blocks, 235 m-blocks), 256 thr. CTA tile 128x128, K chunks of 32.
// Stage layout (40960 B): Ah @0, Al @10240, Bh @20480, Bl @30720; rows 80 B.
#define STG 40960
#define SMEM_GEMM (3 * STG)

__global__ __launch_bounds__(256, 1)
void gemm_mma_kernel(const float* __restrict__ bias) {
    extern __shared__ __align__(16) char dsm[];
    __shared__ float scol[128], scol2[128];

    const int tid = threadIdx.x;
    const int n_block = blockIdx.x * 128;
    const int m_block = blockIdx.y * 128;
    if (tid < 128) { scol[tid] = 0.f; scol2[tid] = 0.f; }

    const uint32_t sbase = (uint32_t)__cvta_generic_to_shared(dsm);

    const int warp = tid >> 5, lane = tid & 31;
    const int wm = warp & 1, wn = warp >> 1;
    const int g = lane >> 2, tg = lane & 3;

    float acc[4][4][4];
    #pragma unroll
    for (int i = 0; i < 4; i++)
        #pragma unroll
        for (int j = 0; j < 4; j++)
            #pragma unroll
            for (int q = 0; q < 4; q++) acc[i][j][q] = 0.f;

    auto issue_chunk = [&](int c) {
        const int buf = c % 3;
        const uint32_t st = sbase + buf * STG;
        const int kc = c * 32;
        const unsigned short *pah, *pal;
        int colb;
        if (c < 24) { pah = g_ah; pal = g_al; colb = kc; }
        else        { pah = g_xh; pal = g_xl; colb = kc - DD; }
        #pragma unroll
        for (int i2 = 0; i2 < 2; i2++) {
            int idx = i2 * 256 + tid;
            int row = idx >> 2, q = idx & 3;
            int grow = m_block + row;
            uint32_t d0 = st + row * 80 + q * 16;
            size_t ga = (size_t)grow * DD + colb + q * 8;
            int sz = (grow < NN) ? 16 : 0;
            cpa16(d0,         pah + ga, sz);
            cpa16(d0 + 10240, pal + ga, sz);
            size_t gb = (size_t)(n_block + row) * K2 + kc + q * 8;
            cpa16(d0 + 20480, g_bh + gb, 16);
            cpa16(d0 + 30720, g_bl + gb, 16);
        }
        CP_COMMIT();
    };

    issue_chunk(0);
    issue_chunk(1);

    for (int c = 0; c < 48; c++) {
        CP_WAIT1();
        __syncthreads();
        if (c + 2 < 48) issue_chunk(c + 2);
        else CP_COMMIT();   // keep group counts consistent

        const char* bufp = dsm + (c % 3) * STG;
        const char* sAh = bufp;
        const char* sAl = bufp + 10240;
        const char* sBh = bufp + 20480;
        const char* sBl = bufp + 30720;

        #pragma unroll
        for (int ks = 0; ks < 2; ks++) {
            const int kb = (ks * 16 + tg * 2) * 2;   // byte offset of this thread's k pair
            uint32_t bh[4][2], bl[4][2];
            #pragma unroll
            for (int j = 0; j < 4; j++) {
                int n = wn * 32 + j * 8 + g;
                const char* ph = sBh + n * 80 + kb;
                const char* pl = sBl + n * 80 + kb;
                bh[j][0] = *(const uint32_t*)ph;  bh[j][1] = *(const uint32_t*)(ph + 16);
                bl[j][0] = *(const uint32_t*)pl;  bl[j][1] = *(const uint32_t*)(pl + 16);
            }
            #pragma unroll
            for (int i = 0; i < 4; i++) {
                int m = wm * 64 + i * 16 + g;
                const char* ph = sAh + m * 80 + kb;
                const char* pl = sAl + m * 80 + kb;
                uint32_t ah0 = *(const uint32_t*)ph;
                uint32_t ah1 = *(const uint32_t*)(ph + 640);
                uint32_t ah2 = *(const uint32_t*)(ph + 16);
                uint32_t ah3 = *(const uint32_t*)(ph + 656);
                uint32_t al0 = *(const uint32_t*)pl;
                uint32_t al1 = *(const uint32_t*)(pl + 640);
                uint32_t al2 = *(const uint32_t*)(pl + 16);
                uint32_t al3 = *(const uint32_t*)(pl + 656);
                #pragma unroll
                for (int j = 0; j < 4; j++) {
                    MMA_BF16(acc[i][j], ah0, ah1, ah2, ah3, bh[j][0], bh[j][1]);
                    MMA_BF16(acc[i][j], al0, al1, al2, al3, bh[j][0], bh[j][1]);
                    MMA_BF16(acc[i][j], ah0, ah1, ah2, ah3, bl[j][0], bl[j][1]);
                }
            }
        }
    }

    // epilogue: bias + relu, plain + cw-weighted column sums (no h store)
    float cw0[4], cw1[4];
    #pragma unroll
    for (int i = 0; i < 4; i++) {
        int r0 = m_block + wm * 64 + i * 16 + g;
        int r1 = r0 + 8;
        cw0[i] = (r0 < NN) ? g_cw[r0] : 0.f;
        cw1[i] = (r1 < NN) ? g_cw[r1] : 0.f;
    }
    #pragma unroll
    for (int j = 0; j < 4; j++) {
        int ncol = wn * 32 + j * 8 + 2 * tg;
        int n0 = n_block + ncol;
        float b0 = bias[n0], b1 = bias[n0 + 1];
        float cs0 = 0.f, cs1 = 0.f, ws0 = 0.f, ws1 = 0.f;
        #pragma unroll
        for (int i = 0; i < 4; i++) {
            int r0 = m_block + wm * 64 + i * 16 + g;
            int r1 = r0 + 8;
            if (r0 < NN) {
                float v0 = fmaxf(acc[i][j][0] + b0, 0.f);
                float v1 = fmaxf(acc[i][j][1] + b1, 0.f);
                cs0 += v0; cs1 += v1;
                ws0 += cw0[i] * v0; ws1 += cw0[i] * v1;
            }
            if (r1 < NN) {
                float v2 = fmaxf(acc[i][j][2] + b0, 0.f);
                float v3 = fmaxf(acc[i][j][3] + b1, 0.f);
                cs0 += v2; cs1 += v3;
                ws0 += cw1[i] * v2; ws1 += cw1[i] * v3;
            }
        }
        atomicAdd(&scol[ncol], cs0);
        atomicAdd(&scol[ncol + 1], cs1);
        atomicAdd(&scol2[ncol], ws0);
        atomicAdd(&scol2[ncol + 1], ws1);
    }
    __syncthreads();
    if (tid < 128) {
        atomicAdd(&g_colsum[n_block + tid], scol[tid]);
        atomicAdd(&g_s2[n_block + tid], scol2[tid]);
    }
}

// ---------------- h rows needed by emb2: var's in-neighbors + var itself ----
// blocks 0..95: segment entries strided; block 96: h[var] -> g_rowvar.
__global__ void var_h_kernel(const int* __restrict__ varp,
                             const float* __restrict__ Wl, const float* __restrict__ Wr,
                             const float* __restrict__ bias) {
    int var = *varp;
    int p0 = g_start[var], p1 = g_start[var + 1];
    float inv = g_inv[var];
    int w = threadIdx.x >> 5, lane = threadIdx.x & 31;
    bool isvar = (blockIdx.x == 96);
    for (int p = p0 + blockIdx.x; isvar || p < p1; p += 96) {
        int row = isvar ? var : g_sorted[p];
        size_t base = (size_t)row * DD;
        for (int j = w; j < DD; j += 8) {
            const float* wl = Wl + (size_t)j * DD;
            const float* wr = Wr + (size_t)j * DD;
            float acc = 0.f;
            for (int k = lane; k < DD; k += 32) {
                float av = bf2f(g_ah[base + k]) + bf2f(g_al[base + k]);
                float xv = bf2f(g_xh[base + k]) + bf2f(g_xl[base + k]);
                acc += av * wl[k] + xv * wr[k];
            }
            #pragma unroll
            for (int o = 16; o; o >>= 1) acc += __shfl_xor_sync(0xffffffffu, acc, o);
            if (lane == 0) {
                float hv = fmaxf(acc + bias[j], 0.f);
                if (isvar) g_rowvar[j] = hv;
                else atomicAdd(&g_agg2var[j], hv * inv);
            }
        }
        if (isvar) break;
    }
}

// ---------------- layer-2 matvecs ----------------
__global__ void matvec2_kernel(const float* __restrict__ Wl, const float* __restrict__ bias,
                               const float* __restrict__ Wr, int mode) {
    const float *a, *b; float s; float* out;
    if (mode == 0)      { a = g_s2;      b = g_colsum; s = 1.0f / NN; out = g_emb1; }
    else if (mode == 1) { a = g_agg2var; b = g_rowvar; s = 1.0f;      out = g_emb2; }
    else                { a = g_s2;      b = g_colsum; s = 1.0f / NN; out = g_embt; }
    int j = blockIdx.x, t = threadIdx.x;   // 128 threads
    const float* wl = Wl + (size_t)j * DD;
    const float* wr = Wr + (size_t)j * DD;
    float p = 0.f;
    for (int k = t; k < DD; k += 128) p += a[k] * wl[k] + b[k] * wr[k];
    #pragma unroll
    for (int o = 16; o; o >>= 1) p += __shfl_xor_sync(0xffffffffu, p, o);
    __shared__ float sw[4];
    if ((t & 31) == 0) sw[t >> 5] = p;
    __syncthreads();
    if (t == 0) out[j] = (sw[0] + sw[1] + sw[2] + sw[3]) * s + bias[j];
}

// ---------------- head ----------------
__global__ void feats_kernel() {
    int t = blockIdx.x * 256 + threadIdx.x;
    if (t < DD) {
        float a = g_emb1[t], b = g_emb2[t];
        g_feats[t] = a; g_feats[DD + t] = b; g_feats[2 * DD + t] = a * b;
    }
}

__global__ void out_kernel(const float* __restrict__ linW, const float* __restrict__ linb,
                           const float* __restrict__ Wo, const float* __restrict__ ov,
                           const int* __restrict__ opp, float* __restrict__ dout) {
    int j = blockIdx.x, t = threadIdx.x;   // 256 threads
    const float* w = linW + (size_t)j * (3 * DD);
    float p = 0.f;
    for (int k = t; k < 3 * DD; k += 256) p += w[k] * g_feats[k];
    #pragma unroll
    for (int o = 16; o; o >>= 1) p += __shfl_xor_sync(0xffffffffu, p, o);
    __shared__ float sw[8];
    if ((t & 31) == 0) sw[t >> 5] = p;
    __syncthreads();
    if (t == 0) {
        float tot = 0.f;
        #pragma unroll
        for (int i = 0; i < 8; i++) tot += sw[i];
        int op = *opp - 1;
        float o = (tot + linb[j]) * Wo[(size_t)op * DD + j];
        float tg = g_embt[j] + ov[(size_t)op * DD + j];
        g_outv[j] = o; g_tgt[j] = tg;
        dout[3 + j] = o;
    }
}

__global__ void final_kernel(const float* __restrict__ labels, float* __restrict__ dout) {
    int t = threadIdx.x;   // 256
    float dd = 0.f, no = 0.f, nt = 0.f;
    for (int j = t; j < DD; j += 256) {
        float o = g_outv[j], g = g_tgt[j];
        dd += o * g; no += o * o; nt += g * g;
    }
    #pragma unroll
    for (int o = 16; o; o >>= 1) {
        dd += __shfl_xor_sync(0xffffffffu, dd, o);
        no += __shfl_xor_sync(0xffffffffu, no, o);
        nt += __shfl_xor_sync(0xffffffffu, nt, o);
    }
    __shared__ float s0[8], s1[8], s2[8];
    if ((t & 31) == 0) { s0[t >> 5] = dd; s1[t >> 5] = no; s2[t >> 5] = nt; }
    __syncthreads();
    if (t == 0) {
        float D_ = 0.f, NO = 0.f, NT = 0.f;
        #pragma unroll
        for (int i = 0; i < 8; i++) { D_ += s0[i]; NO += s1[i]; NT += s2[i]; }
        float n1 = fmaxf(sqrtf(NO), 1e-8f);
        float n2 = fmaxf(sqrtf(NT), 1e-8f);
        float score = D_ / (n1 * n2);
        float lab = labels[0];
        float loss = (score - lab) * (score - lab);
        dout[0] = loss; dout[1] = score; dout[2] = lab;
    }
}

// ---------------- launch ----------------
extern "C" void kernel_launch(void* const* d_in, const int* in_sizes, int n_in,
                              void* d_out, int out_size) {
    (void)in_sizes; (void)n_in; (void)out_size;
    const float* x1   = (const float*)d_in[0];
    const int*   ei1  = (const int*)d_in[1];
    const int*   varp = (const int*)d_in[2];
    const float* xt   = (const float*)d_in[3];
    const int*   eit  = (const int*)d_in[4];
    const int*   opp  = (const int*)d_in[5];
    const float* labels = (const float*)d_in[6];
    const float* Wl1 = (const float*)d_in[7];
    const float* bl1 = (const float*)d_in[8];
    const float* Wr1 = (const float*)d_in[9];
    const float* Wl2 = (const float*)d_in[10];
    const float* bl2 = (const float*)d_in[11];
    const float* Wr2 = (const float*)d_in[12];
    const float* linW = (const float*)d_in[13];
    const float* linb = (const float*)d_in[14];
    const float* Wo  = (const float*)d_in[15];
    const float* ov  = (const float*)d_in[16];
    float* dout = (float*)d_out;

    cudaFuncSetAttribute(gemm_mma_kernel,
                         cudaFuncAttributeMaxDynamicSharedMemorySize, SMEM_GEMM);

    const int EB = (NE + 255) / 256;
    const int XB = ((NN * DD / 8) + 255) / 256;

    convert_b_kernel<<<(DD * K2 + 255) / 256, 256>>>(Wl1, Wr1);

    // ---- graph 1 ----
    zero_graph_kernel<<<118, 256>>>();
    count_kernel<<<EB, 256>>>(ei1);
    prefix_kernel<<<1, 1024>>>();
    place_kernel<<<EB, 256>>>(ei1);
    convert_x_kernel<<<XB, 256>>>(x1);
    gather_agg_kernel<<<dim3(3750, 6), 256>>>(x1);
    gemm_mma_kernel<<<dim3(6, 235), 256, SMEM_GEMM>>>(bl1);
    var_h_kernel<<<97, 256>>>(varp, Wl1, Wr1, bl1);
    matvec2_kernel<<<768, 128>>>(Wl2, bl2, Wr2, 0);   // emb1
    matvec2_kernel<<<768, 128>>>(Wl2, bl2, Wr2, 1);   // emb2

    // ---- graph t ----
    zero_graph_kernel<<<118, 256>>>();
    count_kernel<<<EB, 256>>>(eit);
    prefix_kernel<<<1, 1024>>>();
    place_kernel<<<EB, 256>>>(eit);
    convert_x_kernel<<<XB, 256>>>(xt);
    gather_agg_kernel<<<dim3(3750, 6), 256>>>(xt);
    gemm_mma_kernel<<<dim3(6, 235), 256, SMEM_GEMM>>>(bl1);
    matvec2_kernel<<<768, 128>>>(Wl2, bl2, Wr2, 2);   // embt

    // ---- head ----
    feats_kernel<<<3, 256>>>();
    out_kernel<<<768, 256>>>(linW, linb, Wo, ov, opp, dout);
    final_kernel<<<1, 256>>>(labels, dout);
}

// round 8
// speedup vs baseline: 1.1447x; 1.1447x over previous
#include <cuda_runtime.h>
#include <cuda_fp16.h>
#include <cstdint>

#define NN 30000          // nodes per graph
#define DD 768            // feature dim
#define NE 480000         // edges per graph
#define K2 (2*DD)         // GEMM K = 1536

// ---------------- scratch (static device memory; no allocs) ----------------
__device__ unsigned short g_ah[(size_t)NN * DD];   // fp16 hi of agg (pre-scaled)
__device__ unsigned short g_al[(size_t)NN * DD];   // fp16 lo
__device__ unsigned short g_xh[(size_t)NN * DD];   // fp16 hi of x
__device__ unsigned short g_xl[(size_t)NN * DD];
__device__ unsigned short g_bh[(size_t)DD * K2];   // fp16 of [Wl1|Wr1], row j, col k
__device__ int   g_cnt[NN];
__device__ float g_inv[NN];
__device__ float g_cw[NN];                         // c_j = sum over out-edges of inv[dst]
__device__ int   g_start[NN + 1];
__device__ int   g_cursor[NN];
__device__ int   g_sorted[NE];
__device__ float g_colsum[DD];                     // sum over nodes of h
__device__ float g_s2[DD];                         // sum_j c_j h_j = N*mean(agg2)
__device__ float g_agg2var[DD];
__device__ float g_rowvar[DD];
__device__ float g_emb1[DD], g_emb2[DD], g_embt[DD];
__device__ float g_feats[3 * DD];
__device__ float g_outv[DD], g_tgt[DD];

// ---------------- helpers ----------------
__device__ __forceinline__ unsigned short f2h(float v) {
    __half h = __float2half_rn(v);
    return *reinterpret_cast<unsigned short*>(&h);
}
__device__ __forceinline__ float h2f(unsigned short u) {
    __half h = *reinterpret_cast<__half*>(&u);
    return __half2float(h);
}
__device__ __forceinline__ void cpa16(uint32_t d, const void* s, int sz) {
    asm volatile("cp.async.cg.shared.global [%0], [%1], 16, %2;"
                 :: "r"(d), "l"(s), "r"(sz) : "memory");
}
#define CP_COMMIT() asm volatile("cp.async.commit_group;" ::: "memory")
#define CP_WAIT1()  asm volatile("cp.async.wait_group 1;" ::: "memory")

#define MMA_F16(acc, a0, a1, a2, a3, b0, b1) \
    asm volatile("mma.sync.aligned.m16n8k16.row.col.f32.f16.f16.f32 " \
        "{%0,%1,%2,%3}, {%4,%5,%6,%7}, {%8,%9}, {%0,%1,%2,%3};" \
        : "+f"((acc)[0]), "+f"((acc)[1]), "+f"((acc)[2]), "+f"((acc)[3]) \
        : "r"(a0), "r"(a1), "r"(a2), "r"(a3), "r"(b0), "r"(b1))

// ---------------- graph prep ----------------
__global__ void zero_graph_kernel() {
    int t = blockIdx.x * 256 + threadIdx.x;
    if (t < NN) { g_cnt[t] = 0; g_cw[t] = 0.f; }
    if (t < DD) { g_colsum[t] = 0.f; g_s2[t] = 0.f; g_agg2var[t] = 0.f; }
}

__global__ void count_kernel(const int* __restrict__ ei) {
    int e = blockIdx.x * 256 + threadIdx.x;
    if (e < NE) atomicAdd(&g_cnt[ei[NE + e]], 1);
}

// warp-region scan: 32 warps, each owns a contiguous coalesced region.
#define REG_SZ 938   // ceil(30000/32)
__global__ void prefix_kernel() {
    int tid = threadIdx.x;
    int lane = tid & 31, w = tid >> 5;
    int r0 = w * REG_SZ;
    int r1 = min(r0 + REG_SZ, NN);

    int s = 0;
    for (int idx = r0 + lane; idx < r1; idx += 32) s += g_cnt[idx];
    #pragma unroll
    for (int o = 16; o; o >>= 1) s += __shfl_xor_sync(0xffffffffu, s, o);

    __shared__ int woff[32];
    if (lane == 0) woff[w] = s;
    __syncthreads();
    if (w == 0) {
        int v = woff[lane];
        int iv = v;
        #pragma unroll
        for (int o = 1; o < 32; o <<= 1) {
            int u = __shfl_up_sync(0xffffffffu, iv, o);
            if (lane >= o) iv += u;
        }
        woff[lane] = iv - v;   // exclusive
    }
    __syncthreads();

    int running = woff[w];
    for (int base = r0; base < r1; base += 32) {
        int idx = base + lane;
        int v = (idx < r1) ? g_cnt[idx] : 0;
        int incl = v;
        #pragma unroll
        for (int o = 1; o < 32; o <<= 1) {
            int u = __shfl_up_sync(0xffffffffu, incl, o);
            if (lane >= o) incl += u;
        }
        if (idx < r1) {
            int excl = running + incl - v;
            g_start[idx] = excl;
            g_cursor[idx] = excl;
            g_inv[idx] = 1.0f / (float)max(v, 1);
        }
        running += __shfl_sync(0xffffffffu, incl, 31);
    }
    if (w == 31 && lane == 0) g_start[NN] = running;
}

// placement + c-weight scatter fused
__global__ void place_kernel(const int* __restrict__ ei) {
    int e = blockIdx.x * 256 + threadIdx.x;
    if (e < NE) {
        int s = ei[e], t = ei[NE + e];
        int pos = atomicAdd(&g_cursor[t], 1);
        g_sorted[pos] = s;
        atomicAdd(&g_cw[s], g_inv[t]);
    }
}

// ---------------- weight / x splits ----------------
__global__ void convert_b_kernel(const float* __restrict__ Wl, const float* __restrict__ Wr) {
    int i = blockIdx.x * 256 + threadIdx.x;
    if (i < DD * K2) {
        int j = i / K2, k = i % K2;
        float v = (k < DD) ? Wl[(size_t)j * DD + k] : Wr[(size_t)j * DD + (k - DD)];
        g_bh[i] = f2h(v);
    }
}

__global__ void convert_x_kernel(const float* __restrict__ x) {
    size_t i = ((size_t)blockIdx.x * 256 + threadIdx.x) * 8;
    if (i >= (size_t)NN * DD) return;
    float4 v0 = *(const float4*)(x + i);
    float4 v1 = *(const float4*)(x + i + 4);
    float vv[8] = {v0.x, v0.y, v0.z, v0.w, v1.x, v1.y, v1.z, v1.w};
    unsigned short h[8], l[8];
    #pragma unroll
    for (int j = 0; j < 8; j++) {
        h[j] = f2h(vv[j]);
        l[j] = f2h(vv[j] - h2f(h[j]));
    }
    uint4 H, L;
    H.x = h[0] | ((uint32_t)h[1] << 16); H.y = h[2] | ((uint32_t)h[3] << 16);
    H.z = h[4] | ((uint32_t)h[5] << 16); H.w = h[6] | ((uint32_t)h[7] << 16);
    L.x = l[0] | ((uint32_t)l[1] << 16); L.y = l[2] | ((uint32_t)l[3] << 16);
    L.z = l[4] | ((uint32_t)l[5] << 16); L.w = l[6] | ((uint32_t)l[7] << 16);
    *(uint4*)(g_xh + i) = H;
    *(uint4*)(g_xl + i) = L;
}

// ---------------- layer-1 aggregation: gather by dst segment -> fp16 hi/lo --
__global__ void gather_agg_kernel(const float* __restrict__ x) {
    int warp = threadIdx.x >> 5, lane = threadIdx.x & 31;
    int node = blockIdx.x * 8 + warp;
    int d = blockIdx.y * 128 + lane * 4;
    int p0 = g_start[node], p1 = g_start[node + 1];
    float4 acc = make_float4(0.f, 0.f, 0.f, 0.f);
    int p = p0;
    for (; p + 4 <= p1; p += 4) {
        int s0 = g_sorted[p], s1 = g_sorted[p+1], s2 = g_sorted[p+2], s3 = g_sorted[p+3];
        float4 v0 = *(const float4*)(x + (size_t)s0 * DD + d);
        float4 v1 = *(const float4*)(x + (size_t)s1 * DD + d);
        float4 v2 = *(const float4*)(x + (size_t)s2 * DD + d);
        float4 v3 = *(const float4*)(x + (size_t)s3 * DD + d);
        acc.x += v0.x + v1.x + v2.x + v3.x;
        acc.y += v0.y + v1.y + v2.y + v3.y;
        acc.z += v0.z + v1.z + v2.z + v3.z;
        acc.w += v0.w + v1.w + v2.w + v3.w;
    }
    for (; p < p1; p++) {
        int s = g_sorted[p];
        float4 v = *(const float4*)(x + (size_t)s * DD + d);
        acc.x += v.x; acc.y += v.y; acc.z += v.z; acc.w += v.w;
    }
    float inv = g_inv[node];
    acc.x *= inv; acc.y *= inv; acc.z *= inv; acc.w *= inv;
    ushort4 hv, lv;
    hv.x = f2h(acc.x); lv.x = f2h(acc.x - h2f(hv.x));
    hv.y = f2h(acc.y); lv.y = f2h(acc.y - h2f(hv.y));
    hv.z = f2h(acc.z); lv.z = f2h(acc.z - h2f(hv.z));
    hv.w = f2h(acc.w); lv.w = f2h(acc.w - h2f(hv.w));
    *(ushort4*)(g_ah + (size_t)node * DD + d) = hv;
    *(ushort4*)(g_al + (size_t)node * DD + d) = lv;
}

// ---------------- fp16 2-term mma.sync GEMM, cp.async 3-stage pipeline ------
// h = relu([agg|x] @ Bh^T + b), a split hi/lo, b single fp16.
// grid (6 n-blocks, 235 m-blocks), 256 thr. CTA tile 128x128, K chunks of 32.
// Stage layout (30720 B): Ah @0, Al @10240, Bh @20480; rows 80 B.
#define STG 30720
#define SMEM_GEMM (3 * STG)

__global__ __launch_bounds__(256, 1)
void gemm_mma_kernel(const float* __restrict__ bias) {
    extern __shared__ __align__(16) char dsm[];
    __shared__ float scol[128], scol2[128];

    const int tid = threadIdx.x;
    const int n_block = blockIdx.x * 128;
    const int m_block = blockIdx.y * 128;
    if (tid < 128) { scol[tid] = 0.f; scol2[tid] = 0.f; }

    const uint32_t sbase = (uint32_t)__cvta_generic_to_shared(dsm);

    const int warp = tid >> 5, lane = tid & 31;
    const int wm = warp & 1, wn = warp >> 1;
    const int g = lane >> 2, tg = lane & 3;

    float acc[4][4][4];
    #pragma unroll
    for (int i = 0; i < 4; i++)
        #pragma unroll
        for (int j = 0; j < 4; j++)
            #pragma unroll
            for (int q = 0; q < 4; q++) acc[i][j][q] = 0.f;

    auto issue_chunk = [&](int c) {
        const int buf = c % 3;
        const uint32_t st = sbase + buf * STG;
        const int kc = c * 32;
        const unsigned short *pah, *pal;
        int colb;
        if (c < 24) { pah = g_ah; pal = g_al; colb = kc; }
        else        { pah = g_xh; pal = g_xl; colb = kc - DD; }
        #pragma unroll
        for (int i2 = 0; i2 < 2; i2++) {
            int idx = i2 * 256 + tid;
            int row = idx >> 2, q = idx & 3;
            int grow = m_block + row;
            uint32_t d0 = st + row * 80 + q * 16;
            size_t ga = (size_t)grow * DD + colb + q * 8;
            int sz = (grow < NN) ? 16 : 0;
            cpa16(d0,         pah + ga, sz);
            cpa16(d0 + 10240, pal + ga, sz);
            size_t gb = (size_t)(n_block + row) * K2 + kc + q * 8;
            cpa16(d0 + 20480, g_bh + gb, 16);
        }
        CP_COMMIT();
    };

    issue_chunk(0);
    issue_chunk(1);

    for (int c = 0; c < 48; c++) {
        CP_WAIT1();
        __syncthreads();
        if (c + 2 < 48) issue_chunk(c + 2);
        else CP_COMMIT();   // keep group counts consistent

        const char* bufp = dsm + (c % 3) * STG;
        const char* sAh = bufp;
        const char* sAl = bufp + 10240;
        const char* sBh = bufp + 20480;

        #pragma unroll
        for (int ks = 0; ks < 2; ks++) {
            const int kb = (ks * 16 + tg * 2) * 2;   // byte offset of this thread's k pair
            uint32_t bh[4][2];
            #pragma unroll
            for (int j = 0; j < 4; j++) {
                int n = wn * 32 + j * 8 + g;
                const char* ph = sBh + n * 80 + kb;
                bh[j][0] = *(const uint32_t*)ph;  bh[j][1] = *(const uint32_t*)(ph + 16);
            }
            #pragma unroll
            for (int i = 0; i < 4; i++) {
                int m = wm * 64 + i * 16 + g;
                const char* ph = sAh + m * 80 + kb;
                const char* pl = sAl + m * 80 + kb;
                uint32_t ah0 = *(const uint32_t*)ph;
                uint32_t ah1 = *(const uint32_t*)(ph + 640);
                uint32_t ah2 = *(const uint32_t*)(ph + 16);
                uint32_t ah3 = *(const uint32_t*)(ph + 656);
                uint32_t al0 = *(const uint32_t*)pl;
                uint32_t al1 = *(const uint32_t*)(pl + 640);
                uint32_t al2 = *(const uint32_t*)(pl + 16);
                uint32_t al3 = *(const uint32_t*)(pl + 656);
                #pragma unroll
                for (int j = 0; j < 4; j++) {
                    MMA_F16(acc[i][j], ah0, ah1, ah2, ah3, bh[j][0], bh[j][1]);
                    MMA_F16(acc[i][j], al0, al1, al2, al3, bh[j][0], bh[j][1]);
                }
            }
        }
    }

    // epilogue: bias + relu, plain + cw-weighted column sums (no h store)
    float cw0[4], cw1[4];
    #pragma unroll
    for (int i = 0; i < 4; i++) {
        int r0 = m_block + wm * 64 + i * 16 + g;
        int r1 = r0 + 8;
        cw0[i] = (r0 < NN) ? g_cw[r0] : 0.f;
        cw1[i] = (r1 < NN) ? g_cw[r1] : 0.f;
    }
    #pragma unroll
    for (int j = 0; j < 4; j++) {
        int ncol = wn * 32 + j * 8 + 2 * tg;
        int n0 = n_block + ncol;
        float b0 = bias[n0], b1 = bias[n0 + 1];
        float cs0 = 0.f, cs1 = 0.f, ws0 = 0.f, ws1 = 0.f;
        #pragma unroll
        for (int i = 0; i < 4; i++) {
            int r0 = m_block + wm * 64 + i * 16 + g;
            int r1 = r0 + 8;
            if (r0 < NN) {
                float v0 = fmaxf(acc[i][j][0] + b0, 0.f);
                float v1 = fmaxf(acc[i][j][1] + b1, 0.f);
                cs0 += v0; cs1 += v1;
                ws0 += cw0[i] * v0; ws1 += cw0[i] * v1;
            }
            if (r1 < NN) {
                float v2 = fmaxf(acc[i][j][2] + b0, 0.f);
                float v3 = fmaxf(acc[i][j][3] + b1, 0.f);
                cs0 += v2; cs1 += v3;
                ws0 += cw1[i] * v2; ws1 += cw1[i] * v3;
            }
        }
        atomicAdd(&scol[ncol], cs0);
        atomicAdd(&scol[ncol + 1], cs1);
        atomicAdd(&scol2[ncol], ws0);
        atomicAdd(&scol2[ncol + 1], ws1);
    }
    __syncthreads();
    if (tid < 128) {
        atomicAdd(&g_colsum[n_block + tid], scol[tid]);
        atomicAdd(&g_s2[n_block + tid], scol2[tid]);
    }
}

// ---------------- h rows needed by emb2: var's in-neighbors + var itself ----
// blocks 0..95: segment entries strided; block 96: h[var] -> g_rowvar.
__global__ void var_h_kernel(const int* __restrict__ varp,
                             const float* __restrict__ Wl, const float* __restrict__ Wr,
                             const float* __restrict__ bias) {
    int var = *varp;
    int p0 = g_start[var], p1 = g_start[var + 1];
    float inv = g_inv[var];
    int w = threadIdx.x >> 5, lane = threadIdx.x & 31;
    bool isvar = (blockIdx.x == 96);
    for (int p = p0 + blockIdx.x; isvar || p < p1; p += 96) {
        int row = isvar ? var : g_sorted[p];
        size_t base = (size_t)row * DD;
        for (int j = w; j < DD; j += 8) {
            const float* wl = Wl + (size_t)j * DD;
            const float* wr = Wr + (size_t)j * DD;
            float acc = 0.f;
            for (int k = lane; k < DD; k += 32) {
                float av = h2f(g_ah[base + k]) + h2f(g_al[base + k]);
                float xv = h2f(g_xh[base + k]) + h2f(g_xl[base + k]);
                acc += av * wl[k] + xv * wr[k];
            }
            #pragma unroll
            for (int o = 16; o; o >>= 1) acc += __shfl_xor_sync(0xffffffffu, acc, o);
            if (lane == 0) {
                float hv = fmaxf(acc + bias[j], 0.f);
                if (isvar) g_rowvar[j] = hv;
                else atomicAdd(&g_agg2var[j], hv * inv);
            }
        }
        if (isvar) break;
    }
}

// ---------------- layer-2 matvecs ----------------
__global__ void matvec2_kernel(const float* __restrict__ Wl, const float* __restrict__ bias,
                               const float* __restrict__ Wr, int mode) {
    const float *a, *b; float s; float* out;
    if (mode == 0)      { a = g_s2;      b = g_colsum; s = 1.0f / NN; out = g_emb1; }
    else if (mode == 1) { a = g_agg2var; b = g_rowvar; s = 1.0f;      out = g_emb2; }
    else                { a = g_s2;      b = g_colsum; s = 1.0f / NN; out = g_embt; }
    int j = blockIdx.x, t = threadIdx.x;   // 128 threads
    const float* wl = Wl + (size_t)j * DD;
    const float* wr = Wr + (size_t)j * DD;
    float p = 0.f;
    for (int k = t; k < DD; k += 128) p += a[k] * wl[k] + b[k] * wr[k];
    #pragma unroll
    for (int o = 16; o; o >>= 1) p += __shfl_xor_sync(0xffffffffu, p, o);
    __shared__ float sw[4];
    if ((t & 31) == 0) sw[t >> 5] = p;
    __syncthreads();
    if (t == 0) out[j] = (sw[0] + sw[1] + sw[2] + sw[3]) * s + bias[j];
}

// ---------------- head ----------------
__global__ void feats_kernel() {
    int t = blockIdx.x * 256 + threadIdx.x;
    if (t < DD) {
        float a = g_emb1[t], b = g_emb2[t];
        g_feats[t] = a; g_feats[DD + t] = b; g_feats[2 * DD + t] = a * b;
    }
}

__global__ void out_kernel(const float* __restrict__ linW, const float* __restrict__ linb,
                           const float* __restrict__ Wo, const float* __restrict__ ov,
                           const int* __restrict__ opp, float* __restrict__ dout) {
    int j = blockIdx.x, t = threadIdx.x;   // 256 threads
    const float* w = linW + (size_t)j * (3 * DD);
    float p = 0.f;
    for (int k = t; k < 3 * DD; k += 256) p += w[k] * g_feats[k];
    #pragma unroll
    for (int o = 16; o; o >>= 1) p += __shfl_xor_sync(0xffffffffu, p, o);
    __shared__ float sw[8];
    if ((t & 31) == 0) sw[t >> 5] = p;
    __syncthreads();
    if (t == 0) {
        float tot = 0.f;
        #pragma unroll
        for (int i = 0; i < 8; i++) tot += sw[i];
        int op = *opp - 1;
        float o = (tot + linb[j]) * Wo[(size_t)op * DD + j];
        float tg = g_embt[j] + ov[(size_t)op * DD + j];
        g_outv[j] = o; g_tgt[j] = tg;
        dout[3 + j] = o;
    }
}

__global__ void final_kernel(const float* __restrict__ labels, float* __restrict__ dout) {
    int t = threadIdx.x;   // 256
    float dd = 0.f, no = 0.f, nt = 0.f;
    for (int j = t; j < DD; j += 256) {
        float o = g_outv[j], g = g_tgt[j];
        dd += o * g; no += o * o; nt += g * g;
    }
    #pragma unroll
    for (int o = 16; o; o >>= 1) {
        dd += __shfl_xor_sync(0xffffffffu, dd, o);
        no += __shfl_xor_sync(0xffffffffu, no, o);
        nt += __shfl_xor_sync(0xffffffffu, nt, o);
    }
    __shared__ float s0[8], s1[8], s2[8];
    if ((t & 31) == 0) { s0[t >> 5] = dd; s1[t >> 5] = no; s2[t >> 5] = nt; }
    __syncthreads();
    if (t == 0) {
        float D_ = 0.f, NO = 0.f, NT = 0.f;
        #pragma unroll
        for (int i = 0; i < 8; i++) { D_ += s0[i]; NO += s1[i]; NT += s2[i]; }
        float n1 = fmaxf(sqrtf(NO), 1e-8f);
        float n2 = fmaxf(sqrtf(NT), 1e-8f);
        float score = D_ / (n1 * n2);
        float lab = labels[0];
        float loss = (score - lab) * (score - lab);
        dout[0] = loss; dout[1] = score; dout[2] = lab;
    }
}

// ---------------- launch ----------------
extern "C" void kernel_launch(void* const* d_in, const int* in_sizes, int n_in,
                              void* d_out, int out_size) {
    (void)in_sizes; (void)n_in; (void)out_size;
    const float* x1   = (const float*)d_in[0];
    const int*   ei1  = (const int*)d_in[1];
    const int*   varp = (const int*)d_in[2];
    const float* xt   = (const float*)d_in[3];
    const int*   eit  = (const int*)d_in[4];
    const int*   opp  = (const int*)d_in[5];
    const float* labels = (const float*)d_in[6];
    const float* Wl1 = (const float*)d_in[7];
    const float* bl1 = (const float*)d_in[8];
    const float* Wr1 = (const float*)d_in[9];
    const float* Wl2 = (const float*)d_in[10];
    const float* bl2 = (const float*)d_in[11];
    const float* Wr2 = (const float*)d_in[12];
    const float* linW = (const float*)d_in[13];
    const float* linb = (const float*)d_in[14];
    const float* Wo  = (const float*)d_in[15];
    const float* ov  = (const float*)d_in[16];
    float* dout = (float*)d_out;

    static bool attr_set = false;
    if (!attr_set) {
        cudaFuncSetAttribute(gemm_mma_kernel,
                             cudaFuncAttributeMaxDynamicSharedMemorySize, SMEM_GEMM);
        attr_set = true;
    }

    const int EB = (NE + 255) / 256;
    const int XB = ((NN * DD / 8) + 255) / 256;

    convert_b_kernel<<<(DD * K2 + 255) / 256, 256>>>(Wl1, Wr1);

    // ---- graph 1 ----
    zero_graph_kernel<<<118, 256>>>();
    count_kernel<<<EB, 256>>>(ei1);
    prefix_kernel<<<1, 1024>>>();
    place_kernel<<<EB, 256>>>(ei1);
    convert_x_kernel<<<XB, 256>>>(x1);
    gather_agg_kernel<<<dim3(3750, 6), 256>>>(x1);
    gemm_mma_kernel<<<dim3(6, 235), 256, SMEM_GEMM>>>(bl1);
    var_h_kernel<<<97, 256>>>(varp, Wl1, Wr1, bl1);
    matvec2_kernel<<<768, 128>>>(Wl2, bl2, Wr2, 0);   // emb1
    matvec2_kernel<<<768, 128>>>(Wl2, bl2, Wr2, 1);   // emb2

    // ---- graph t ----
    zero_graph_kernel<<<118, 256>>>();
    count_kernel<<<EB, 256>>>(eit);
    prefix_kernel<<<1, 1024>>>();
    place_kernel<<<EB, 256>>>(eit);
    convert_x_kernel<<<XB, 256>>>(xt);
    gather_agg_kernel<<<dim3(3750, 6), 256>>>(xt);
    gemm_mma_kernel<<<dim3(6, 235), 256, SMEM_GEMM>>>(bl1);
    matvec2_kernel<<<768, 128>>>(Wl2, bl2, Wr2, 2);   // embt

    // ---- head ----
    feats_kernel<<<3, 256>>>();
    out_kernel<<<768, 256>>>(linW, linb, Wo, ov, opp, dout);
    final_kernel<<<1, 256>>>(labels, dout);
}

// round 10
// speedup vs baseline: 1.3861x; 1.2108x over previous
#include <cuda_runtime.h>
#include <cuda_fp16.h>
#include <cstdint>

#define NN 30000          // nodes per graph
#define DD 768            // feature dim
#define NE 480000         // edges per graph
#define K2 (2*DD)         // GEMM K = 1536
#define NND ((size_t)NN * DD)

// ---------------- scratch (static device memory; no allocs) ----------------
// all per-graph arrays doubled: [graph0 | graph1]
__device__ unsigned short g_ah[2 * NND];           // fp16 hi of agg (pre-scaled)
__device__ unsigned short g_al[2 * NND];           // fp16 lo of agg (var_h only)
__device__ unsigned short g_xh[2 * NND];           // fp16 hi of x
__device__ unsigned short g_bh[(size_t)DD * K2];   // fp16 of [Wl1|Wr1], row j, col k
__device__ int   g_cnt[2 * NN];
__device__ float g_inv[2 * NN];
__device__ float g_cw[2 * NN];                     // c_j = sum over out-edges of inv[dst]
__device__ int   g_start[2 * (NN + 1)];
__device__ int   g_cursor[2 * NN];
__device__ int   g_sorted[2 * NE];
__device__ float g_colsum[2 * DD];                 // per-graph sum over nodes of h
__device__ float g_s2[2 * DD];                     // per-graph sum_j c_j h_j
__device__ float g_agg2var[DD];
__device__ float g_rowvar[DD];
__device__ float g_emb1[DD], g_emb2[DD], g_embt[DD];
__device__ float g_feats[3 * DD];
__device__ float g_outv[DD], g_tgt[DD];

// ---------------- helpers ----------------
__device__ __forceinline__ unsigned short f2h(float v) {
    __half h = __float2half_rn(v);
    return *reinterpret_cast<unsigned short*>(&h);
}
__device__ __forceinline__ float h2f(unsigned short u) {
    __half h = *reinterpret_cast<__half*>(&u);
    return __half2float(h);
}
__device__ __forceinline__ void cpa16(uint32_t d, const void* s, int sz) {
    asm volatile("cp.async.cg.shared.global [%0], [%1], 16, %2;"
                 :: "r"(d), "l"(s), "r"(sz) : "memory");
}
#define CP_COMMIT() asm volatile("cp.async.commit_group;" ::: "memory")
#define CP_WAIT1()  asm volatile("cp.async.wait_group 1;" ::: "memory")

#define MMA_F16(acc, a0, a1, a2, a3, b0, b1) \
    asm volatile("mma.sync.aligned.m16n8k16.row.col.f32.f16.f16.f32 " \
        "{%0,%1,%2,%3}, {%4,%5,%6,%7}, {%8,%9}, {%0,%1,%2,%3};" \
        : "+f"((acc)[0]), "+f"((acc)[1]), "+f"((acc)[2]), "+f"((acc)[3]) \
        : "r"(a0), "r"(a1), "r"(a2), "r"(a3), "r"(b0), "r"(b1))

// ---------------- graph prep (batched over both graphs) ----------------
__global__ void zero_graph_kernel() {
    int t = blockIdx.x * 256 + threadIdx.x;
    if (t < 2 * NN) { g_cnt[t] = 0; g_cw[t] = 0.f; }
    if (t < 2 * DD) { g_colsum[t] = 0.f; g_s2[t] = 0.f; }
    if (t < DD) g_agg2var[t] = 0.f;
}

__global__ void count_kernel(const int* __restrict__ e0, const int* __restrict__ e1) {
    int e = blockIdx.x * 256 + threadIdx.x;
    int gi = blockIdx.y;
    const int* ei = gi ? e1 : e0;
    if (e < NE) atomicAdd(&g_cnt[gi * NN + ei[NE + e]], 1);
}

// warp-region scan per graph (blockIdx.x = graph), 1024 threads
#define REG_SZ 938   // ceil(30000/32)
__global__ void prefix_kernel() {
    int gi = blockIdx.x;
    int C = gi * NN, S = gi * (NN + 1);
    int tid = threadIdx.x;
    int lane = tid & 31, w = tid >> 5;
    int r0 = w * REG_SZ;
    int r1 = min(r0 + REG_SZ, NN);

    int s = 0;
    for (int idx = r0 + lane; idx < r1; idx += 32) s += g_cnt[C + idx];
    #pragma unroll
    for (int o = 16; o; o >>= 1) s += __shfl_xor_sync(0xffffffffu, s, o);

    __shared__ int woff[32];
    if (lane == 0) woff[w] = s;
    __syncthreads();
    if (w == 0) {
        int v = woff[lane];
        int iv = v;
        #pragma unroll
        for (int o = 1; o < 32; o <<= 1) {
            int u = __shfl_up_sync(0xffffffffu, iv, o);
            if (lane >= o) iv += u;
        }
        woff[lane] = iv - v;   // exclusive
    }
    __syncthreads();

    int running = woff[w];
    for (int base = r0; base < r1; base += 32) {
        int idx = base + lane;
        int v = (idx < r1) ? g_cnt[C + idx] : 0;
        int incl = v;
        #pragma unroll
        for (int o = 1; o < 32; o <<= 1) {
            int u = __shfl_up_sync(0xffffffffu, incl, o);
            if (lane >= o) incl += u;
        }
        if (idx < r1) {
            int excl = running + incl - v;
            g_start[S + idx] = excl;
            g_cursor[C + idx] = excl;
            g_inv[C + idx] = 1.0f / (float)max(v, 1);
        }
        running += __shfl_sync(0xffffffffu, incl, 31);
    }
    if (w == 31 && lane == 0) g_start[S + NN] = running;
}

// placement + c-weight scatter fused
__global__ void place_kernel(const int* __restrict__ e0, const int* __restrict__ e1) {
    int e = blockIdx.x * 256 + threadIdx.x;
    int gi = blockIdx.y;
    const int* ei = gi ? e1 : e0;
    if (e < NE) {
        int s = ei[e], t = ei[NE + e];
        int pos = atomicAdd(&g_cursor[gi * NN + t], 1);
        g_sorted[gi * NE + pos] = s;
        atomicAdd(&g_cw[gi * NN + s], g_inv[gi * NN + t]);
    }
}

// ---------------- weight / x conversion ----------------
__global__ void convert_b_kernel(const float* __restrict__ Wl, const float* __restrict__ Wr) {
    int i = blockIdx.x * 256 + threadIdx.x;
    if (i < DD * K2) {
        int j = i / K2, k = i % K2;
        float v = (k < DD) ? Wl[(size_t)j * DD + k] : Wr[(size_t)j * DD + (k - DD)];
        g_bh[i] = f2h(v);
    }
}

__global__ void convert_x_kernel(const float* __restrict__ x0, const float* __restrict__ x1) {
    size_t i = ((size_t)blockIdx.x * 256 + threadIdx.x) * 8;
    if (i >= NND) return;
    int gi = blockIdx.y;
    const float* x = gi ? x1 : x0;
    float4 v0 = *(const float4*)(x + i);
    float4 v1 = *(const float4*)(x + i + 4);
    float vv[8] = {v0.x, v0.y, v0.z, v0.w, v1.x, v1.y, v1.z, v1.w};
    unsigned short h[8];
    #pragma unroll
    for (int j = 0; j < 8; j++) h[j] = f2h(vv[j]);
    uint4 H;
    H.x = h[0] | ((uint32_t)h[1] << 16); H.y = h[2] | ((uint32_t)h[3] << 16);
    H.z = h[4] | ((uint32_t)h[5] << 16); H.w = h[6] | ((uint32_t)h[7] << 16);
    *(uint4*)(g_xh + gi * NND + i) = H;
}

// ---------------- layer-1 aggregation: gather by dst segment -> fp16 hi/lo --
__global__ void gather_agg_kernel(const float* __restrict__ x0, const float* __restrict__ x1) {
    int gi = blockIdx.z;
    const float* x = gi ? x1 : x0;
    const int* sorted = g_sorted + gi * NE;
    int warp = threadIdx.x >> 5, lane = threadIdx.x & 31;
    int node = blockIdx.x * 8 + warp;
    int d = blockIdx.y * 128 + lane * 4;
    int p0 = g_start[gi * (NN + 1) + node], p1 = g_start[gi * (NN + 1) + node + 1];
    float4 acc = make_float4(0.f, 0.f, 0.f, 0.f);
    int p = p0;
    for (; p + 4 <= p1; p += 4) {
        int s0 = sorted[p], s1 = sorted[p+1], s2 = sorted[p+2], s3 = sorted[p+3];
        float4 v0 = *(const float4*)(x + (size_t)s0 * DD + d);
        float4 v1 = *(const float4*)(x + (size_t)s1 * DD + d);
        float4 v2 = *(const float4*)(x + (size_t)s2 * DD + d);
        float4 v3 = *(const float4*)(x + (size_t)s3 * DD + d);
        acc.x += v0.x + v1.x + v2.x + v3.x;
        acc.y += v0.y + v1.y + v2.y + v3.y;
        acc.z += v0.z + v1.z + v2.z + v3.z;
        acc.w += v0.w + v1.w + v2.w + v3.w;
    }
    for (; p < p1; p++) {
        int s = sorted[p];
        float4 v = *(const float4*)(x + (size_t)s * DD + d);
        acc.x += v.x; acc.y += v.y; acc.z += v.z; acc.w += v.w;
    }
    float inv = g_inv[gi * NN + node];
    acc.x *= inv; acc.y *= inv; acc.z *= inv; acc.w *= inv;
    ushort4 hv, lv;
    hv.x = f2h(acc.x); lv.x = f2h(acc.x - h2f(hv.x));
    hv.y = f2h(acc.y); lv.y = f2h(acc.y - h2f(hv.y));
    hv.z = f2h(acc.z); lv.z = f2h(acc.z - h2f(hv.z));
    hv.w = f2h(acc.w); lv.w = f2h(acc.w - h2f(hv.w));
    size_t o = gi * NND + (size_t)node * DD + d;
    *(ushort4*)(g_ah + o) = hv;
    *(ushort4*)(g_al + o) = lv;
}

// ---------------- fp16 single-term mma.sync GEMM, cp.async 3-stage ----------
// h = relu(ah @ bh^T + bias) with fp32 accumulate; A-rounding error averages
// out across nodes in colsum/s2 (the only consumers of this GEMM).
// grid (6 n-blocks, 235 m-blocks, 2 graphs), 256 thr. CTA tile 128x128, K=32/chunk.
// Stage layout (20480 B): Ah @0, Bh @10240; rows 80 B.
#define STG 20480
#define SMEM_GEMM (3 * STG)

__global__ __launch_bounds__(256, 1)
void gemm_mma_kernel(const float* __restrict__ bias) {
    extern __shared__ __align__(16) char dsm[];
    __shared__ float scol[128], scol2[128];

    const int tid = threadIdx.x;
    const int n_block = blockIdx.x * 128;
    const int m_block = blockIdx.y * 128;
    const int gi = blockIdx.z;
    const size_t goff = (size_t)gi * NND;
    if (tid < 128) { scol[tid] = 0.f; scol2[tid] = 0.f; }

    const uint32_t sbase = (uint32_t)__cvta_generic_to_shared(dsm);

    const int warp = tid >> 5, lane = tid & 31;
    const int wm = warp & 1, wn = warp >> 1;
    const int g = lane >> 2, tg = lane & 3;

    float acc[4][4][4];
    #pragma unroll
    for (int i = 0; i < 4; i++)
        #pragma unroll
        for (int j = 0; j < 4; j++)
            #pragma unroll
            for (int q = 0; q < 4; q++) acc[i][j][q] = 0.f;

    auto issue_chunk = [&](int c) {
        const int buf = c % 3;
        const uint32_t st = sbase + buf * STG;
        const int kc = c * 32;
        const unsigned short* pah;
        int colb;
        if (c < 24) { pah = g_ah + goff; colb = kc; }
        else        { pah = g_xh + goff; colb = kc - DD; }
        #pragma unroll
        for (int i2 = 0; i2 < 2; i2++) {
            int idx = i2 * 256 + tid;
            int row = idx >> 2, q = idx & 3;
            int grow = m_block + row;
            uint32_t d0 = st + row * 80 + q * 16;
            size_t ga = (size_t)grow * DD + colb + q * 8;
            int sz = (grow < NN) ? 16 : 0;
            cpa16(d0, pah + ga, sz);
            size_t gb = (size_t)(n_block + row) * K2 + kc + q * 8;
            cpa16(d0 + 10240, g_bh + gb, 16);
        }
        CP_COMMIT();
    };

    issue_chunk(0);
    issue_chunk(1);

    for (int c = 0; c < 48; c++) {
        CP_WAIT1();
        __syncthreads();
        if (c + 2 < 48) issue_chunk(c + 2);
        else CP_COMMIT();   // keep group counts consistent

        const char* bufp = dsm + (c % 3) * STG;
        const char* sAh = bufp;
        const char* sBh = bufp + 10240;

        #pragma unroll
        for (int ks = 0; ks < 2; ks++) {
            const int kb = (ks * 16 + tg * 2) * 2;   // byte offset of this thread's k pair
            uint32_t bh[4][2];
            #pragma unroll
            for (int j = 0; j < 4; j++) {
                int n = wn * 32 + j * 8 + g;
                const char* ph = sBh + n * 80 + kb;
                bh[j][0] = *(const uint32_t*)ph;  bh[j][1] = *(const uint32_t*)(ph + 16);
            }
            #pragma unroll
            for (int i = 0; i < 4; i++) {
                int m = wm * 64 + i * 16 + g;
                const char* ph = sAh + m * 80 + kb;
                uint32_t ah0 = *(const uint32_t*)ph;
                uint32_t ah1 = *(const uint32_t*)(ph + 640);
                uint32_t ah2 = *(const uint32_t*)(ph + 16);
                uint32_t ah3 = *(const uint32_t*)(ph + 656);
                #pragma unroll
                for (int j = 0; j < 4; j++)
                    MMA_F16(acc[i][j], ah0, ah1, ah2, ah3, bh[j][0], bh[j][1]);
            }
        }
    }

    // epilogue: bias + relu, plain + cw-weighted column sums (no h store)
    const float* cwp = g_cw + gi * NN;
    float cw0[4], cw1[4];
    #pragma unroll
    for (int i = 0; i < 4; i++) {
        int r0 = m_block + wm * 64 + i * 16 + g;
        int r1 = r0 + 8;
        cw0[i] = (r0 < NN) ? cwp[r0] : 0.f;
        cw1[i] = (r1 < NN) ? cwp[r1] : 0.f;
    }
    #pragma unroll
    for (int j = 0; j < 4; j++) {
        int ncol = wn * 32 + j * 8 + 2 * tg;
        int n0 = n_block + ncol;
        float b0 = bias[n0], b1 = bias[n0 + 1];
        float cs0 = 0.f, cs1 = 0.f, ws0 = 0.f, ws1 = 0.f;
        #pragma unroll
        for (int i = 0; i < 4; i++) {
            int r0 = m_block + wm * 64 + i * 16 + g;
            int r1 = r0 + 8;
            if (r0 < NN) {
                float v0 = fmaxf(acc[i][j][0] + b0, 0.f);
                float v1 = fmaxf(acc[i][j][1] + b1, 0.f);
                cs0 += v0; cs1 += v1;
                ws0 += cw0[i] * v0; ws1 += cw0[i] * v1;
            }
            if (r1 < NN) {
                float v2 = fmaxf(acc[i][j][2] + b0, 0.f);
                float v3 = fmaxf(acc[i][j][3] + b1, 0.f);
                cs0 += v2; cs1 += v3;
                ws0 += cw1[i] * v2; ws1 += cw1[i] * v3;
            }
        }
        atomicAdd(&scol[ncol], cs0);
        atomicAdd(&scol[ncol + 1], cs1);
        atomicAdd(&scol2[ncol], ws0);
        atomicAdd(&scol2[ncol + 1], ws1);
    }
    __syncthreads();
    if (tid < 128) {
        atomicAdd(&g_colsum[gi * DD + n_block + tid], scol[tid]);
        atomicAdd(&g_s2[gi * DD + n_block + tid], scol2[tid]);
    }
}

// ---------------- h rows needed by emb2 (graph 0): var's in-neighbors + var -
// High precision: agg from fp16 hi+lo pair, x and weights in fp32.
__global__ void var_h_kernel(const int* __restrict__ varp, const float* __restrict__ x,
                             const float* __restrict__ Wl, const float* __restrict__ Wr,
                             const float* __restrict__ bias) {
    int var = *varp;
    int p0 = g_start[var], p1 = g_start[var + 1];
    float inv = g_inv[var];
    int w = threadIdx.x >> 5, lane = threadIdx.x & 31;
    bool isvar = (blockIdx.x == 96);
    for (int p = p0 + blockIdx.x; isvar || p < p1; p += 96) {
        int row = isvar ? var : g_sorted[p];
        size_t base = (size_t)row * DD;
        for (int j = w; j < DD; j += 8) {
            const float* wl = Wl + (size_t)j * DD;
            const float* wr = Wr + (size_t)j * DD;
            float acc = 0.f;
            for (int k = lane; k < DD; k += 32) {
                float av = h2f(g_ah[base + k]) + h2f(g_al[base + k]);
                acc += av * wl[k] + x[base + k] * wr[k];
            }
            #pragma unroll
            for (int o = 16; o; o >>= 1) acc += __shfl_xor_sync(0xffffffffu, acc, o);
            if (lane == 0) {
                float hv = fmaxf(acc + bias[j], 0.f);
                if (isvar) g_rowvar[j] = hv;
                else atomicAdd(&g_agg2var[j], hv * inv);
            }
        }
        if (isvar) break;
    }
}

// ---------------- layer-2 matvecs: all 3 in one launch (grid 768 x 3) ------
__global__ void matvec2_kernel(const float* __restrict__ Wl, const float* __restrict__ bias,
                               const float* __restrict__ Wr) {
    int mode = blockIdx.y;
    const float *a, *b; float s; float* out;
    if (mode == 0)      { a = g_s2;      b = g_colsum;      s = 1.0f / NN; out = g_emb1; }
    else if (mode == 1) { a = g_agg2var; b = g_rowvar;      s = 1.0f;      out = g_emb2; }
    else                { a = g_s2 + DD; b = g_colsum + DD; s = 1.0f / NN; out = g_embt; }
    int j = blockIdx.x, t = threadIdx.x;   // 128 threads
    const float* wl = Wl + (size_t)j * DD;
    const float* wr = Wr + (size_t)j * DD;
    float p = 0.f;
    for (int k = t; k < DD; k += 128) p += a[k] * wl[k] + b[k] * wr[k];
    #pragma unroll
    for (int o = 16; o; o >>= 1) p += __shfl_xor_sync(0xffffffffu, p, o);
    __shared__ float sw[4];
    if ((t & 31) == 0) sw[t >> 5] = p;
    __syncthreads();
    if (t == 0) out[j] = (sw[0] + sw[1] + sw[2] + sw[3]) * s + bias[j];
}

// ---------------- head ----------------
__global__ void feats_kernel() {
    int t = blockIdx.x * 256 + threadIdx.x;
    if (t < DD) {
        float a = g_emb1[t], b = g_emb2[t];
        g_feats[t] = a; g_feats[DD + t] = b; g_feats[2 * DD + t] = a * b;
    }
}

__global__ void out_kernel(const float* __restrict__ linW, const float* __restrict__ linb,
                           const float* __restrict__ Wo, const float* __restrict__ ov,
                           const int* __restrict__ opp, float* __restrict__ dout) {
    int j = blockIdx.x, t = threadIdx.x;   // 256 threads
    const float* w = linW + (size_t)j * (3 * DD);
    float p = 0.f;
    for (int k = t; k < 3 * DD; k += 256) p += w[k] * g_feats[k];
    #pragma unroll
    for (int o = 16; o; o >>= 1) p += __shfl_xor_sync(0xffffffffu, p, o);
    __shared__ float sw[8];
    if ((t & 31) == 0) sw[t >> 5] = p;
    __syncthreads();
    if (t == 0) {
        float tot = 0.f;
        #pragma unroll
        for (int i = 0; i < 8; i++) tot += sw[i];
        int op = *opp - 1;
        float o = (tot + linb[j]) * Wo[(size_t)op * DD + j];
        float tg = g_embt[j] + ov[(size_t)op * DD + j];
        g_outv[j] = o; g_tgt[j] = tg;
        dout[3 + j] = o;
    }
}

__global__ void final_kernel(const float* __restrict__ labels, float* __restrict__ dout) {
    int t = threadIdx.x;   // 256
    float dd = 0.f, no = 0.f, nt = 0.f;
    for (int j = t; j < DD; j += 256) {
        float o = g_outv[j], g = g_tgt[j];
        dd += o * g; no += o * o; nt += g * g;
    }
    #pragma unroll
    for (int o = 16; o; o >>= 1) {
        dd += __shfl_xor_sync(0xffffffffu, dd, o);
        no += __shfl_xor_sync(0xffffffffu, no, o);
        nt += __shfl_xor_sync(0xffffffffu, nt, o);
    }
    __shared__ float s0[8], s1[8], s2[8];
    if ((t & 31) == 0) { s0[t >> 5] = dd; s1[t >> 5] = no; s2[t >> 5] = nt; }
    __syncthreads();
    if (t == 0) {
        float D_ = 0.f, NO = 0.f, NT = 0.f;
        #pragma unroll
        for (int i = 0; i < 8; i++) { D_ += s0[i]; NO += s1[i]; NT += s2[i]; }
        float n1 = fmaxf(sqrtf(NO), 1e-8f);
        float n2 = fmaxf(sqrtf(NT), 1e-8f);
        float score = D_ / (n1 * n2);
        float lab = labels[0];
        float loss = (score - lab) * (score - lab);
        dout[0] = loss; dout[1] = score; dout[2] = lab;
    }
}

// ---------------- launch ----------------
extern "C" void kernel_launch(void* const* d_in, const int* in_sizes, int n_in,
                              void* d_out, int out_size) {
    (void)in_sizes; (void)n_in; (void)out_size;
    const float* x1   = (const float*)d_in[0];
    const int*   ei1  = (const int*)d_in[1];
    const int*   varp = (const int*)d_in[2];
    const float* xt   = (const float*)d_in[3];
    const int*   eit  = (const int*)d_in[4];
    const int*   opp  = (const int*)d_in[5];
    const float* labels = (const float*)d_in[6];
    const float* Wl1 = (const float*)d_in[7];
    const float* bl1 = (const float*)d_in[8];
    const float* Wr1 = (const float*)d_in[9];
    const float* Wl2 = (const float*)d_in[10];
    const float* bl2 = (const float*)d_in[11];
    const float* Wr2 = (const float*)d_in[12];
    const float* linW = (const float*)d_in[13];
    const float* linb = (const float*)d_in[14];
    const float* Wo  = (const float*)d_in[15];
    const float* ov  = (const float*)d_in[16];
    float* dout = (float*)d_out;

    static bool attr_set = false;
    if (!attr_set) {
        cudaFuncSetAttribute(gemm_mma_kernel,
                             cudaFuncAttributeMaxDynamicSharedMemorySize, SMEM_GEMM);
        attr_set = true;
    }

    const int EB = (NE + 255) / 256;
    const int XB = (int)((NND / 8 + 255) / 256);

    convert_b_kernel<<<(DD * K2 + 255) / 256, 256>>>(Wl1, Wr1);
    zero_graph_kernel<<<(2 * NN + 255) / 256, 256>>>();
    count_kernel<<<dim3(EB, 2), 256>>>(ei1, eit);
    prefix_kernel<<<2, 1024>>>();
    place_kernel<<<dim3(EB, 2), 256>>>(ei1, eit);
    convert_x_kernel<<<dim3(XB, 2), 256>>>(x1, xt);
    gather_agg_kernel<<<dim3(3750, 6, 2), 256>>>(x1, xt);
    var_h_kernel<<<97, 256>>>(varp, x1, Wl1, Wr1, bl1);
    gemm_mma_kernel<<<dim3(6, 235, 2), 256, SMEM_GEMM>>>(bl1);
    matvec2_kernel<<<dim3(768, 3), 128>>>(Wl2, bl2, Wr2);
    feats_kernel<<<3, 256>>>();
    out_kernel<<<768, 256>>>(linW, linb, Wo, ov, opp, dout);
    final_kernel<<<1, 256>>>(labels, dout);
}

// round 13
// speedup vs baseline: 1.4149x; 1.0208x over previous
#include <cuda_runtime.h>
#include <cuda_fp16.h>
#include <cstdint>

#define NN 30000          // nodes per graph
#define DD 768            // feature dim
#define NE 480000         // edges per graph
#define K2 (2*DD)         // GEMM K = 1536
#define NND ((size_t)NN * DD)

// ---------------- scratch (static device memory; no allocs) ----------------
// all per-graph arrays doubled: [graph0 | graph1]
__device__ unsigned short g_ah[2 * NND];           // fp16 hi of agg (pre-scaled)
__device__ unsigned short g_al[2 * NND];           // fp16 lo of agg (var_h only)
__device__ unsigned short g_xh[2 * NND];           // fp16 of x
__device__ unsigned short g_bh[(size_t)DD * K2];   // fp16 of [Wl1|Wr1], row j, col k
__device__ int   g_cnt[2 * NN];
__device__ float g_inv[2 * NN];
__device__ float g_cw[2 * NN];                     // c_j = sum over out-edges of inv[dst]
__device__ int   g_start[2 * (NN + 1)];
__device__ int   g_cursor[2 * NN];
__device__ int   g_sorted[2 * NE];
__device__ float g_colsum[2 * DD];                 // per-graph sum over nodes of h
__device__ float g_s2[2 * DD];                     // per-graph sum_j c_j h_j
__device__ float g_agg2var[DD];
__device__ float g_rowvar[DD];
__device__ float g_emb1[DD], g_emb2[DD], g_embt[DD];
__device__ float g_feats[3 * DD];
__device__ float g_outv[DD], g_tgt[DD];

// ---------------- helpers ----------------
__device__ __forceinline__ unsigned short f2h(float v) {
    __half h = __float2half_rn(v);
    return *reinterpret_cast<unsigned short*>(&h);
}
__device__ __forceinline__ float h2f(unsigned short u) {
    __half h = *reinterpret_cast<__half*>(&u);
    return __half2float(h);
}
__device__ __forceinline__ void cpa16(uint32_t d, const void* s, int sz) {
    asm volatile("cp.async.cg.shared.global [%0], [%1], 16, %2;"
                 :: "r"(d), "l"(s), "r"(sz) : "memory");
}
#define CP_COMMIT() asm volatile("cp.async.commit_group;" ::: "memory")
#define CP_WAIT1()  asm volatile("cp.async.wait_group 1;" ::: "memory")

#define MMA_F16(acc, a0, a1, a2, a3, b0, b1) \
    asm volatile("mma.sync.aligned.m16n8k16.row.col.f32.f16.f16.f32 " \
        "{%0,%1,%2,%3}, {%4,%5,%6,%7}, {%8,%9}, {%0,%1,%2,%3};" \
        : "+f"((acc)[0]), "+f"((acc)[1]), "+f"((acc)[2]), "+f"((acc)[3]) \
        : "r"(a0), "r"(a1), "r"(a2), "r"(a3), "r"(b0), "r"(b1))

// ---------------- graph prep (batched over both graphs) ----------------
__global__ void zero_graph_kernel() {
    int t = blockIdx.x * 256 + threadIdx.x;
    if (t < 2 * NN) { g_cnt[t] = 0; g_cw[t] = 0.f; }
    if (t < 2 * DD) { g_colsum[t] = 0.f; g_s2[t] = 0.f; }
    if (t < DD) g_agg2var[t] = 0.f;
}

__global__ void count_kernel(const int* __restrict__ e0, const int* __restrict__ e1) {
    int e = blockIdx.x * 256 + threadIdx.x;
    int gi = blockIdx.y;
    const int* ei = gi ? e1 : e0;
    if (e < NE) atomicAdd(&g_cnt[gi * NN + ei[NE + e]], 1);
}

// warp-region scan per graph (blockIdx.x = graph), 1024 threads
#define REG_SZ 938   // ceil(30000/32)
__global__ void prefix_kernel() {
    int gi = blockIdx.x;
    int C = gi * NN, S = gi * (NN + 1);
    int tid = threadIdx.x;
    int lane = tid & 31, w = tid >> 5;
    int r0 = w * REG_SZ;
    int r1 = min(r0 + REG_SZ, NN);

    int s = 0;
    for (int idx = r0 + lane; idx < r1; idx += 32) s += g_cnt[C + idx];
    #pragma unroll
    for (int o = 16; o; o >>= 1) s += __shfl_xor_sync(0xffffffffu, s, o);

    __shared__ int woff[32];
    if (lane == 0) woff[w] = s;
    __syncthreads();
    if (w == 0) {
        int v = woff[lane];
        int iv = v;
        #pragma unroll
        for (int o = 1; o < 32; o <<= 1) {
            int u = __shfl_up_sync(0xffffffffu, iv, o);
            if (lane >= o) iv += u;
        }
        woff[lane] = iv - v;   // exclusive
    }
    __syncthreads();

    int running = woff[w];
    for (int base = r0; base < r1; base += 32) {
        int idx = base + lane;
        int v = (idx < r1) ? g_cnt[C + idx] : 0;
        int incl = v;
        #pragma unroll
        for (int o = 1; o < 32; o <<= 1) {
            int u = __shfl_up_sync(0xffffffffu, incl, o);
            if (lane >= o) incl += u;
        }
        if (idx < r1) {
            int excl = running + incl - v;
            g_start[S + idx] = excl;
            g_cursor[C + idx] = excl;
            g_inv[C + idx] = 1.0f / (float)max(v, 1);
        }
        running += __shfl_sync(0xffffffffu, incl, 31);
    }
    if (w == 31 && lane == 0) g_start[S + NN] = running;
}

// placement + c-weight scatter fused
__global__ void place_kernel(const int* __restrict__ e0, const int* __restrict__ e1) {
    int e = blockIdx.x * 256 + threadIdx.x;
    int gi = blockIdx.y;
    const int* ei = gi ? e1 : e0;
    if (e < NE) {
        int s = ei[e], t = ei[NE + e];
        int pos = atomicAdd(&g_cursor[gi * NN + t], 1);
        g_sorted[gi * NE + pos] = s;
        atomicAdd(&g_cw[gi * NN + s], g_inv[gi * NN + t]);
    }
}

// ---------------- weight / x conversion ----------------
__global__ void convert_b_kernel(const float* __restrict__ Wl, const float* __restrict__ Wr) {
    int i = blockIdx.x * 256 + threadIdx.x;
    if (i < DD * K2) {
        int j = i / K2, k = i % K2;
        float v = (k < DD) ? Wl[(size_t)j * DD + k] : Wr[(size_t)j * DD + (k - DD)];
        g_bh[i] = f2h(v);
    }
}

__global__ void convert_x_kernel(const float* __restrict__ x0, const float* __restrict__ x1) {
    size_t i = ((size_t)blockIdx.x * 256 + threadIdx.x) * 8;
    if (i >= NND) return;
    int gi = blockIdx.y;
    const float* x = gi ? x1 : x0;
    float4 v0 = *(const float4*)(x + i);
    float4 v1 = *(const float4*)(x + i + 4);
    float vv[8] = {v0.x, v0.y, v0.z, v0.w, v1.x, v1.y, v1.z, v1.w};
    unsigned short h[8];
    #pragma unroll
    for (int j = 0; j < 8; j++) h[j] = f2h(vv[j]);
    uint4 H;
    H.x = h[0] | ((uint32_t)h[1] << 16); H.y = h[2] | ((uint32_t)h[3] << 16);
    H.z = h[4] | ((uint32_t)h[5] << 16); H.w = h[6] | ((uint32_t)h[7] << 16);
    *(uint4*)(g_xh + gi * NND + i) = H;
}

// ---------------- layer-1 aggregation: gather fp16 x by dst segment --------
// grid (3750, 3, 2): warp per node, 256 fp16 cols per y-chunk. fp32 accumulate.
// Emits hi/lo fp16 pair (lo consumed only by var_h_kernel).
__global__ void gather_agg_kernel() {
    int gi = blockIdx.z;
    const unsigned short* xh = g_xh + (size_t)gi * NND;
    const int* sorted = g_sorted + gi * NE;
    int warp = threadIdx.x >> 5, lane = threadIdx.x & 31;
    int node = blockIdx.x * 8 + warp;
    int d = blockIdx.y * 256 + lane * 8;
    int p0 = g_start[gi * (NN + 1) + node], p1 = g_start[gi * (NN + 1) + node + 1];
    float acc[8] = {0.f, 0.f, 0.f, 0.f, 0.f, 0.f, 0.f, 0.f};
    auto addrow = [&](int s) {
        uint4 v = *(const uint4*)(xh + (size_t)s * DD + d);
        const __half2* hp = reinterpret_cast<const __half2*>(&v);
        #pragma unroll
        for (int q = 0; q < 4; q++) {
            float2 f = __half22float2(hp[q]);
            acc[2 * q] += f.x; acc[2 * q + 1] += f.y;
        }
    };
    int p = p0;
    for (; p + 4 <= p1; p += 4) {
        int s0 = sorted[p], s1 = sorted[p + 1], s2 = sorted[p + 2], s3 = sorted[p + 3];
        addrow(s0); addrow(s1); addrow(s2); addrow(s3);
    }
    for (; p < p1; p++) addrow(sorted[p]);
    float inv = g_inv[gi * NN + node];
    unsigned short hv[8], lv[8];
    #pragma unroll
    for (int q = 0; q < 8; q++) {
        float v = acc[q] * inv;
        hv[q] = f2h(v);
        lv[q] = f2h(v - h2f(hv[q]));
    }
    uint4 H, L;
    H.x = hv[0] | ((uint32_t)hv[1] << 16); H.y = hv[2] | ((uint32_t)hv[3] << 16);
    H.z = hv[4] | ((uint32_t)hv[5] << 16); H.w = hv[6] | ((uint32_t)hv[7] << 16);
    L.x = lv[0] | ((uint32_t)lv[1] << 16); L.y = lv[2] | ((uint32_t)lv[3] << 16);
    L.z = lv[4] | ((uint32_t)lv[5] << 16); L.w = lv[6] | ((uint32_t)lv[7] << 16);
    size_t o = (size_t)gi * NND + (size_t)node * DD + d;
    *(uint4*)(g_ah + o) = H;
    *(uint4*)(g_al + o) = L;
}

// ---------------- fp16 single-term mma.sync GEMM, cp.async 3-stage ----------
// h = relu(ah @ bh^T + bias) with fp32 accumulate; A-rounding error averages
// out across nodes in colsum/s2 (the only consumers of this GEMM).
// grid (6 n-blocks, 235 m-blocks, 2 graphs), 256 thr. CTA tile 128x128, K=32/chunk.
// Stage layout (20480 B): Ah @0, Bh @10240; rows 80 B.
#define STG 20480
#define SMEM_GEMM (3 * STG)

__global__ __launch_bounds__(256, 1)
void gemm_mma_kernel(const float* __restrict__ bias) {
    extern __shared__ __align__(16) char dsm[];
    __shared__ float scol[128], scol2[128];

    const int tid = threadIdx.x;
    const int n_block = blockIdx.x * 128;
    const int m_block = blockIdx.y * 128;
    const int gi = blockIdx.z;
    const size_t goff = (size_t)gi * NND;
    if (tid < 128) { scol[tid] = 0.f; scol2[tid] = 0.f; }

    const uint32_t sbase = (uint32_t)__cvta_generic_to_shared(dsm);

    const int warp = tid >> 5, lane = tid & 31;
    const int wm = warp & 1, wn = warp >> 1;
    const int g = lane >> 2, tg = lane & 3;

    float acc[4][4][4];
    #pragma unroll
    for (int i = 0; i < 4; i++)
        #pragma unroll
        for (int j = 0; j < 4; j++)
            #pragma unroll
            for (int q = 0; q < 4; q++) acc[i][j][q] = 0.f;

    auto issue_chunk = [&](int c) {
        const int buf = c % 3;
        const uint32_t st = sbase + buf * STG;
        const int kc = c * 32;
        const unsigned short* pah;
        int colb;
        if (c < 24) { pah = g_ah + goff; colb = kc; }
        else        { pah = g_xh + goff; colb = kc - DD; }
        #pragma unroll
        for (int i2 = 0; i2 < 2; i2++) {
            int idx = i2 * 256 + tid;
            int row = idx >> 2, q = idx & 3;
            int grow = m_block + row;
            uint32_t d0 = st + row * 80 + q * 16;
            size_t ga = (size_t)grow * DD + colb + q * 8;
            int sz = (grow < NN) ? 16 : 0;
            cpa16(d0, pah + ga, sz);
            size_t gb = (size_t)(n_block + row) * K2 + kc + q * 8;
            cpa16(d0 + 10240, g_bh + gb, 16);
        }
        CP_COMMIT();
    };

    issue_chunk(0);
    issue_chunk(1);

    for (int c = 0; c < 48; c++) {
        CP_WAIT1();
        __syncthreads();
        if (c + 2 < 48) issue_chunk(c + 2);
        else CP_COMMIT();   // keep group counts consistent

        const char* bufp = dsm + (c % 3) * STG;
        const char* sAh = bufp;
        const char* sBh = bufp + 10240;

        #pragma unroll
        for (int ks = 0; ks < 2; ks++) {
            const int kb = (ks * 16 + tg * 2) * 2;   // byte offset of this thread's k pair
            uint32_t bh[4][2];
            #pragma unroll
            for (int j = 0; j < 4; j++) {
                int n = wn * 32 + j * 8 + g;
                const char* ph = sBh + n * 80 + kb;
                bh[j][0] = *(const uint32_t*)ph;  bh[j][1] = *(const uint32_t*)(ph + 16);
            }
            #pragma unroll
            for (int i = 0; i < 4; i++) {
                int m = wm * 64 + i * 16 + g;
                const char* ph = sAh + m * 80 + kb;
                uint32_t ah0 = *(const uint32_t*)ph;
                uint32_t ah1 = *(const uint32_t*)(ph + 640);
                uint32_t ah2 = *(const uint32_t*)(ph + 16);
                uint32_t ah3 = *(const uint32_t*)(ph + 656);
                #pragma unroll
                for (int j = 0; j < 4; j++)
                    MMA_F16(acc[i][j], ah0, ah1, ah2, ah3, bh[j][0], bh[j][1]);
            }
        }
    }

    // epilogue: bias + relu, plain + cw-weighted column sums (no h store)
    const float* cwp = g_cw + gi * NN;
    float cw0[4], cw1[4];
    #pragma unroll
    for (int i = 0; i < 4; i++) {
        int r0 = m_block + wm * 64 + i * 16 + g;
        int r1 = r0 + 8;
        cw0[i] = (r0 < NN) ? cwp[r0] : 0.f;
        cw1[i] = (r1 < NN) ? cwp[r1] : 0.f;
    }
    #pragma unroll
    for (int j = 0; j < 4; j++) {
        int ncol = wn * 32 + j * 8 + 2 * tg;
        int n0 = n_block + ncol;
        float b0 = bias[n0], b1 = bias[n0 + 1];
        float cs0 = 0.f, cs1 = 0.f, ws0 = 0.f, ws1 = 0.f;
        #pragma unroll
        for (int i = 0; i < 4; i++) {
            int r0 = m_block + wm * 64 + i * 16 + g;
            int r1 = r0 + 8;
            if (r0 < NN) {
                float v0 = fmaxf(acc[i][j][0] + b0, 0.f);
                float v1 = fmaxf(acc[i][j][1] + b1, 0.f);
                cs0 += v0; cs1 += v1;
                ws0 += cw0[i] * v0; ws1 += cw0[i] * v1;
            }
            if (r1 < NN) {
                float v2 = fmaxf(acc[i][j][2] + b0, 0.f);
                float v3 = fmaxf(acc[i][j][3] + b1, 0.f);
                cs0 += v2; cs1 += v3;
                ws0 += cw1[i] * v2; ws1 += cw1[i] * v3;
            }
        }
        atomicAdd(&scol[ncol], cs0);
        atomicAdd(&scol[ncol + 1], cs1);
        atomicAdd(&scol2[ncol], ws0);
        atomicAdd(&scol2[ncol + 1], ws1);
    }
    __syncthreads();
    if (tid < 128) {
        atomicAdd(&g_colsum[gi * DD + n_block + tid], scol[tid]);
        atomicAdd(&g_s2[gi * DD + n_block + tid], scol2[tid]);
    }
}

// ---------------- h rows needed by emb2 (graph 0): var's in-neighbors + var -
// Agg from fp16 hi+lo pair, x and weights in fp32 (R10 structure).
__global__ void var_h_kernel(const int* __restrict__ varp, const float* __restrict__ x,
                             const float* __restrict__ Wl, const float* __restrict__ Wr,
                             const float* __restrict__ bias) {
    int var = *varp;
    int p0 = g_start[var], p1 = g_start[var + 1];
    float inv = g_inv[var];
    int w = threadIdx.x >> 5, lane = threadIdx.x & 31;
    bool isvar = (blockIdx.x == 96);
    for (int p = p0 + blockIdx.x; isvar || p < p1; p += 96) {
        int row = isvar ? var : g_sorted[p];
        size_t base = (size_t)row * DD;
        for (int j = w; j < DD; j += 8) {
            const float* wl = Wl + (size_t)j * DD;
            const float* wr = Wr + (size_t)j * DD;
            float acc = 0.f;
            for (int k = lane; k < DD; k += 32) {
                float av = h2f(g_ah[base + k]) + h2f(g_al[base + k]);
                acc += av * wl[k] + x[base + k] * wr[k];
            }
            #pragma unroll
            for (int o = 16; o; o >>= 1) acc += __shfl_xor_sync(0xffffffffu, acc, o);
            if (lane == 0) {
                float hv = fmaxf(acc + bias[j], 0.f);
                if (isvar) g_rowvar[j] = hv;
                else atomicAdd(&g_agg2var[j], hv * inv);
            }
        }
        if (isvar) break;
    }
}

// ---------------- layer-2 matvecs: all 3 in one launch (grid 768 x 3) ------
__global__ void matvec2_kernel(const float* __restrict__ Wl, const float* __restrict__ bias,
                               const float* __restrict__ Wr) {
    int mode = blockIdx.y;
    const float *a, *b; float s; float* out;
    if (mode == 0)      { a = g_s2;      b = g_colsum;      s = 1.0f / NN; out = g_emb1; }
    else if (mode == 1) { a = g_agg2var; b = g_rowvar;      s = 1.0f;      out = g_emb2; }
    else                { a = g_s2 + DD; b = g_colsum + DD; s = 1.0f / NN; out = g_embt; }
    int j = blockIdx.x, t = threadIdx.x;   // 128 threads
    const float* wl = Wl + (size_t)j * DD;
    const float* wr = Wr + (size_t)j * DD;
    float p = 0.f;
    for (int k = t; k < DD; k += 128) p += a[k] * wl[k] + b[k] * wr[k];
    #pragma unroll
    for (int o = 16; o; o >>= 1) p += __shfl_xor_sync(0xffffffffu, p, o);
    __shared__ float sw[4];
    if ((t & 31) == 0) sw[t >> 5] = p;
    __syncthreads();
    if (t == 0) out[j] = (sw[0] + sw[1] + sw[2] + sw[3]) * s + bias[j];
}

// ---------------- head ----------------
__global__ void feats_kernel() {
    int t = blockIdx.x * 256 + threadIdx.x;
    if (t < DD) {
        float a = g_emb1[t], b = g_emb2[t];
        g_feats[t] = a; g_feats[DD + t] = b; g_feats[2 * DD + t] = a * b;
    }
}

__global__ void out_kernel(const float* __restrict__ linW, const float* __restrict__ linb,
                           const float* __restrict__ Wo, const float* __restrict__ ov,
                           const int* __restrict__ opp, float* __restrict__ dout) {
    int j = blockIdx.x, t = threadIdx.x;   // 256 threads
    const float* w = linW + (size_t)j * (3 * DD);
    float p = 0.f;
    for (int k = t; k < 3 * DD; k += 256) p += w[k] * g_feats[k];
    #pragma unroll
    for (int o = 16; o; o >>= 1) p += __shfl_xor_sync(0xffffffffu, p, o);
    __shared__ float sw[8];
    if ((t & 31) == 0) sw[t >> 5] = p;
    __syncthreads();
    if (t == 0) {
        float tot = 0.f;
        #pragma unroll
        for (int i = 0; i < 8; i++) tot += sw[i];
        int op = *opp - 1;
        float o = (tot + linb[j]) * Wo[(size_t)op * DD + j];
        float tg = g_embt[j] + ov[(size_t)op * DD + j];
        g_outv[j] = o; g_tgt[j] = tg;
        dout[3 + j] = o;
    }
}

__global__ void final_kernel(const float* __restrict__ labels, float* __restrict__ dout) {
    int t = threadIdx.x;   // 256
    float dd = 0.f, no = 0.f, nt = 0.f;
    for (int j = t; j < DD; j += 256) {
        float o = g_outv[j], g = g_tgt[j];
        dd += o * g; no += o * o; nt += g * g;
    }
    #pragma unroll
    for (int o = 16; o; o >>= 1) {
        dd += __shfl_xor_sync(0xffffffffu, dd, o);
        no += __shfl_xor_sync(0xffffffffu, no, o);
        nt += __shfl_xor_sync(0xffffffffu, nt, o);
    }
    __shared__ float s0[8], s1[8], s2[8];
    if ((t & 31) == 0) { s0[t >> 5] = dd; s1[t >> 5] = no; s2[t >> 5] = nt; }
    __syncthreads();
    if (t == 0) {
        float D_ = 0.f, NO = 0.f, NT = 0.f;
        #pragma unroll
        for (int i = 0; i < 8; i++) { D_ += s0[i]; NO += s1[i]; NT += s2[i]; }
        float n1 = fmaxf(sqrtf(NO), 1e-8f);
        float n2 = fmaxf(sqrtf(NT), 1e-8f);
        float score = D_ / (n1 * n2);
        float lab = labels[0];
        float loss = (score - lab) * (score - lab);
        dout[0] = loss; dout[1] = score; dout[2] = lab;
    }
}

// ---------------- launch ----------------
extern "C" void kernel_launch(void* const* d_in, const int* in_sizes, int n_in,
                              void* d_out, int out_size) {
    (void)in_sizes; (void)n_in; (void)out_size;
    const float* x1   = (const float*)d_in[0];
    const int*   ei1  = (const int*)d_in[1];
    const int*   varp = (const int*)d_in[2];
    const float* xt   = (const float*)d_in[3];
    const int*   eit  = (const int*)d_in[4];
    const int*   opp  = (const int*)d_in[5];
    const float* labels = (const float*)d_in[6];
    const float* Wl1 = (const float*)d_in[7];
    const float* bl1 = (const float*)d_in[8];
    const float* Wr1 = (const float*)d_in[9];
    const float* Wl2 = (const float*)d_in[10];
    const float* bl2 = (const float*)d_in[11];
    const float* Wr2 = (const float*)d_in[12];
    const float* linW = (const float*)d_in[13];
    const float* linb = (const float*)d_in[14];
    const float* Wo  = (const float*)d_in[15];
    const float* ov  = (const float*)d_in[16];
    float* dout = (float*)d_out;

    static bool attr_set = false;
    if (!attr_set) {
        cudaFuncSetAttribute(gemm_mma_kernel,
                             cudaFuncAttributeMaxDynamicSharedMemorySize, SMEM_GEMM);
        attr_set = true;
    }

    const int EB = (NE + 255) / 256;
    const int XB = (int)((NND / 8 + 255) / 256);

    convert_b_kernel<<<(DD * K2 + 255) / 256, 256>>>(Wl1, Wr1);
    zero_graph_kernel<<<(2 * NN + 255) / 256, 256>>>();
    count_kernel<<<dim3(EB, 2), 256>>>(ei1, eit);
    prefix_kernel<<<2, 1024>>>();
    place_kernel<<<dim3(EB, 2), 256>>>(ei1, eit);
    convert_x_kernel<<<dim3(XB, 2), 256>>>(x1, xt);
    gather_agg_kernel<<<dim3(3750, 3, 2), 256>>>();
    var_h_kernel<<<97, 256>>>(varp, x1, Wl1, Wr1, bl1);
    gemm_mma_kernel<<<dim3(6, 235, 2), 256, SMEM_GEMM>>>(bl1);
    matvec2_kernel<<<dim3(768, 3), 128>>>(Wl2, bl2, Wr2);
    feats_kernel<<<3, 256>>>();
    out_kernel<<<768, 256>>>(linW, linb, Wo, ov, opp, dout);
    final_kernel<<<1, 256>>>(labels, dout);
}

// round 16
// speedup vs baseline: 1.4202x; 1.0037x over previous
#include <cuda_runtime.h>
#include <cuda_fp16.h>
#include <cstdint>

#define NN 30000          // nodes per graph
#define DD 768            // feature dim
#define NE 480000         // edges per graph
#define K2 (2*DD)         // GEMM K = 1536
#define NND ((size_t)NN * DD)

// ---------------- scratch (static device memory; no allocs) ----------------
// all per-graph arrays doubled: [graph0 | graph1]
__device__ unsigned short g_ah[2 * NND];           // fp16 hi of agg (pre-scaled)
__device__ unsigned short g_al[2 * NND];           // fp16 lo of agg (var_h only)
__device__ unsigned short g_xh[2 * NND];           // fp16 of x
__device__ unsigned short g_bh[(size_t)DD * K2];   // fp16 of [Wl1|Wr1], row j, col k
__device__ int   g_cnt[2 * NN];
__device__ float g_inv[2 * NN];
__device__ float g_cw[2 * NN];                     // c_j = sum over out-edges of inv[dst]
__device__ int   g_start[2 * (NN + 1)];
__device__ int   g_cursor[2 * NN];
__device__ int   g_sorted[2 * NE];
__device__ float g_colsum[2 * DD];                 // per-graph sum over nodes of h
__device__ float g_s2[2 * DD];                     // per-graph sum_j c_j h_j
__device__ float g_agg2var[DD];
__device__ float g_rowvar[DD];
__device__ float g_emb1[DD], g_emb2[DD], g_embt[DD];
__device__ float g_outv[DD], g_tgt[DD];

// ---------------- helpers ----------------
__device__ __forceinline__ unsigned short f2h(float v) {
    __half h = __float2half_rn(v);
    return *reinterpret_cast<unsigned short*>(&h);
}
__device__ __forceinline__ float h2f(unsigned short u) {
    __half h = *reinterpret_cast<__half*>(&u);
    return __half2float(h);
}
__device__ __forceinline__ void cpa16(uint32_t d, const void* s, int sz) {
    asm volatile("cp.async.cg.shared.global [%0], [%1], 16, %2;"
                 :: "r"(d), "l"(s), "r"(sz) : "memory");
}
#define CP_COMMIT() asm volatile("cp.async.commit_group;" ::: "memory")
#define CP_WAIT1()  asm volatile("cp.async.wait_group 1;" ::: "memory")

#define MMA_F16(acc, a0, a1, a2, a3, b0, b1) \
    asm volatile("mma.sync.aligned.m16n8k16.row.col.f32.f16.f16.f32 " \
        "{%0,%1,%2,%3}, {%4,%5,%6,%7}, {%8,%9}, {%0,%1,%2,%3};" \
        : "+f"((acc)[0]), "+f"((acc)[1]), "+f"((acc)[2]), "+f"((acc)[3]) \
        : "r"(a0), "r"(a1), "r"(a2), "r"(a3), "r"(b0), "r"(b1))

// ---------------- graph prep (batched over both graphs) ----------------
__global__ void zero_graph_kernel() {
    int t = blockIdx.x * 256 + threadIdx.x;
    if (t < 2 * NN) { g_cnt[t] = 0; g_cw[t] = 0.f; }
    if (t < 2 * DD) { g_colsum[t] = 0.f; g_s2[t] = 0.f; }
    if (t < DD) g_agg2var[t] = 0.f;
}

__global__ void count_kernel(const int* __restrict__ e0, const int* __restrict__ e1) {
    int e = blockIdx.x * 256 + threadIdx.x;
    int gi = blockIdx.y;
    const int* ei = gi ? e1 : e0;
    if (e < NE) atomicAdd(&g_cnt[gi * NN + ei[NE + e]], 1);
}

// warp-region scan per graph (blockIdx.x = graph), 1024 threads
#define REG_SZ 938   // ceil(30000/32)
__global__ void prefix_kernel() {
    int gi = blockIdx.x;
    int C = gi * NN, S = gi * (NN + 1);
    int tid = threadIdx.x;
    int lane = tid & 31, w = tid >> 5;
    int r0 = w * REG_SZ;
    int r1 = min(r0 + REG_SZ, NN);

    int s = 0;
    for (int idx = r0 + lane; idx < r1; idx += 32) s += g_cnt[C + idx];
    #pragma unroll
    for (int o = 16; o; o >>= 1) s += __shfl_xor_sync(0xffffffffu, s, o);

    __shared__ int woff[32];
    if (lane == 0) woff[w] = s;
    __syncthreads();
    if (w == 0) {
        int v = woff[lane];
        int iv = v;
        #pragma unroll
        for (int o = 1; o < 32; o <<= 1) {
            int u = __shfl_up_sync(0xffffffffu, iv, o);
            if (lane >= o) iv += u;
        }
        woff[lane] = iv - v;   // exclusive
    }
    __syncthreads();

    int running = woff[w];
    for (int base = r0; base < r1; base += 32) {
        int idx = base + lane;
        int v = (idx < r1) ? g_cnt[C + idx] : 0;
        int incl = v;
        #pragma unroll
        for (int o = 1; o < 32; o <<= 1) {
            int u = __shfl_up_sync(0xffffffffu, incl, o);
            if (lane >= o) incl += u;
        }
        if (idx < r1) {
            int excl = running + incl - v;
            g_start[S + idx] = excl;
            g_cursor[C + idx] = excl;
            g_inv[C + idx] = 1.0f / (float)max(v, 1);
        }
        running += __shfl_sync(0xffffffffu, incl, 31);
    }
    if (w == 31 && lane == 0) g_start[S + NN] = running;
}

// placement + c-weight scatter fused
__global__ void place_kernel(const int* __restrict__ e0, const int* __restrict__ e1) {
    int e = blockIdx.x * 256 + threadIdx.x;
    int gi = blockIdx.y;
    const int* ei = gi ? e1 : e0;
    if (e < NE) {
        int s = ei[e], t = ei[NE + e];
        int pos = atomicAdd(&g_cursor[gi * NN + t], 1);
        g_sorted[gi * NE + pos] = s;
        atomicAdd(&g_cw[gi * NN + s], g_inv[gi * NN + t]);
    }
}

// ---------------- weight / x conversion ----------------
__global__ void convert_b_kernel(const float* __restrict__ Wl, const float* __restrict__ Wr) {
    int i = blockIdx.x * 256 + threadIdx.x;
    if (i < DD * K2) {
        int j = i / K2, k = i % K2;
        float v = (k < DD) ? Wl[(size_t)j * DD + k] : Wr[(size_t)j * DD + (k - DD)];
        g_bh[i] = f2h(v);
    }
}

__global__ void convert_x_kernel(const float* __restrict__ x0, const float* __restrict__ x1) {
    size_t i = ((size_t)blockIdx.x * 256 + threadIdx.x) * 8;
    if (i >= NND) return;
    int gi = blockIdx.y;
    const float* x = gi ? x1 : x0;
    float4 v0 = *(const float4*)(x + i);
    float4 v1 = *(const float4*)(x + i + 4);
    float vv[8] = {v0.x, v0.y, v0.z, v0.w, v1.x, v1.y, v1.z, v1.w};
    unsigned short h[8];
    #pragma unroll
    for (int j = 0; j < 8; j++) h[j] = f2h(vv[j]);
    uint4 H;
    H.x = h[0] | ((uint32_t)h[1] << 16); H.y = h[2] | ((uint32_t)h[3] << 16);
    H.z = h[4] | ((uint32_t)h[5] << 16); H.w = h[6] | ((uint32_t)h[7] << 16);
    *(uint4*)(g_xh + gi * NND + i) = H;
}

// ---------------- layer-1 aggregation: gather fp16 x by dst segment --------
// grid (3750, 3, 2): warp per node, 256 fp16 cols per y-chunk. fp32 accumulate.
// Emits hi/lo fp16 pair (lo consumed only by var_h_kernel).
__global__ void gather_agg_kernel() {
    int gi = blockIdx.z;
    const unsigned short* xh = g_xh + (size_t)gi * NND;
    const int* sorted = g_sorted + gi * NE;
    int warp = threadIdx.x >> 5, lane = threadIdx.x & 31;
    int node = blockIdx.x * 8 + warp;
    int d = blockIdx.y * 256 + lane * 8;
    int p0 = g_start[gi * (NN + 1) + node], p1 = g_start[gi * (NN + 1) + node + 1];
    float acc[8] = {0.f, 0.f, 0.f, 0.f, 0.f, 0.f, 0.f, 0.f};
    auto addrow = [&](int s) {
        uint4 v = *(const uint4*)(xh + (size_t)s * DD + d);
        const __half2* hp = reinterpret_cast<const __half2*>(&v);
        #pragma unroll
        for (int q = 0; q < 4; q++) {
            float2 f = __half22float2(hp[q]);
            acc[2 * q] += f.x; acc[2 * q + 1] += f.y;
        }
    };
    int p = p0;
    for (; p + 4 <= p1; p += 4) {
        int s0 = sorted[p], s1 = sorted[p + 1], s2 = sorted[p + 2], s3 = sorted[p + 3];
        addrow(s0); addrow(s1); addrow(s2); addrow(s3);
    }
    for (; p < p1; p++) addrow(sorted[p]);
    float inv = g_inv[gi * NN + node];
    unsigned short hv[8], lv[8];
    #pragma unroll
    for (int q = 0; q < 8; q++) {
        float v = acc[q] * inv;
        hv[q] = f2h(v);
        lv[q] = f2h(v - h2f(hv[q]));
    }
    uint4 H, L;
    H.x = hv[0] | ((uint32_t)hv[1] << 16); H.y = hv[2] | ((uint32_t)hv[3] << 16);
    H.z = hv[4] | ((uint32_t)hv[5] << 16); H.w = hv[6] | ((uint32_t)hv[7] << 16);
    L.x = lv[0] | ((uint32_t)lv[1] << 16); L.y = lv[2] | ((uint32_t)lv[3] << 16);
    L.z = lv[4] | ((uint32_t)lv[5] << 16); L.w = lv[6] | ((uint32_t)lv[7] << 16);
    size_t o = (size_t)gi * NND + (size_t)node * DD + d;
    *(uint4*)(g_ah + o) = H;
    *(uint4*)(g_al + o) = L;
}

// ---------------- fp16 single-term mma.sync GEMM, cp.async 3-stage ----------
// h = relu(ah @ bh^T + bias) with fp32 accumulate; A-rounding error averages
// out across nodes in colsum/s2 (the only consumers of this GEMM).
// grid (6 n-blocks, 235 m-blocks, 2 graphs), 256 thr. CTA tile 128x128, K=32/chunk.
// Stage layout (20480 B): Ah @0, Bh @10240; rows 80 B.
#define STG 20480
#define SMEM_GEMM (3 * STG)

__global__ __launch_bounds__(256, 1)
void gemm_mma_kernel(const float* __restrict__ bias) {
    extern __shared__ __align__(16) char dsm[];
    __shared__ float scol[128], scol2[128];

    const int tid = threadIdx.x;
    const int n_block = blockIdx.x * 128;
    const int m_block = blockIdx.y * 128;
    const int gi = blockIdx.z;
    const size_t goff = (size_t)gi * NND;
    if (tid < 128) { scol[tid] = 0.f; scol2[tid] = 0.f; }

    const uint32_t sbase = (uint32_t)__cvta_generic_to_shared(dsm);

    const int warp = tid >> 5, lane = tid & 31;
    const int wm = warp & 1, wn = warp >> 1;
    const int g = lane >> 2, tg = lane & 3;

    float acc[4][4][4];
    #pragma unroll
    for (int i = 0; i < 4; i++)
        #pragma unroll
        for (int j = 0; j < 4; j++)
            #pragma unroll
            for (int q = 0; q < 4; q++) acc[i][j][q] = 0.f;

    auto issue_chunk = [&](int c) {
        const int buf = c % 3;
        const uint32_t st = sbase + buf * STG;
        const int kc = c * 32;
        const unsigned short* pah;
        int colb;
        if (c < 24) { pah = g_ah + goff; colb = kc; }
        else        { pah = g_xh + goff; colb = kc - DD; }
        #pragma unroll
        for (int i2 = 0; i2 < 2; i2++) {
            int idx = i2 * 256 + tid;
            int row = idx >> 2, q = idx & 3;
            int grow = m_block + row;
            uint32_t d0 = st + row * 80 + q * 16;
            size_t ga = (size_t)grow * DD + colb + q * 8;
            int sz = (grow < NN) ? 16 : 0;
            cpa16(d0, pah + ga, sz);
            size_t gb = (size_t)(n_block + row) * K2 + kc + q * 8;
            cpa16(d0 + 10240, g_bh + gb, 16);
        }
        CP_COMMIT();
    };

    issue_chunk(0);
    issue_chunk(1);

    for (int c = 0; c < 48; c++) {
        CP_WAIT1();
        __syncthreads();
        if (c + 2 < 48) issue_chunk(c + 2);
        else CP_COMMIT();   // keep group counts consistent

        const char* bufp = dsm + (c % 3) * STG;
        const char* sAh = bufp;
        const char* sBh = bufp + 10240;

        #pragma unroll
        for (int ks = 0; ks < 2; ks++) {
            const int kb = (ks * 16 + tg * 2) * 2;   // byte offset of this thread's k pair
            uint32_t bh[4][2];
            #pragma unroll
            for (int j = 0; j < 4; j++) {
                int n = wn * 32 + j * 8 + g;
                const char* ph = sBh + n * 80 + kb;
                bh[j][0] = *(const uint32_t*)ph;  bh[j][1] = *(const uint32_t*)(ph + 16);
            }
            #pragma unroll
            for (int i = 0; i < 4; i++) {
                int m = wm * 64 + i * 16 + g;
                const char* ph = sAh + m * 80 + kb;
                uint32_t ah0 = *(const uint32_t*)ph;
                uint32_t ah1 = *(const uint32_t*)(ph + 640);
                uint32_t ah2 = *(const uint32_t*)(ph + 16);
                uint32_t ah3 = *(const uint32_t*)(ph + 656);
                #pragma unroll
                for (int j = 0; j < 4; j++)
                    MMA_F16(acc[i][j], ah0, ah1, ah2, ah3, bh[j][0], bh[j][1]);
            }
        }
    }

    // epilogue: bias + relu, plain + cw-weighted column sums (no h store)
    const float* cwp = g_cw + gi * NN;
    float cw0[4], cw1[4];
    #pragma unroll
    for (int i = 0; i < 4; i++) {
        int r0 = m_block + wm * 64 + i * 16 + g;
        int r1 = r0 + 8;
        cw0[i] = (r0 < NN) ? cwp[r0] : 0.f;
        cw1[i] = (r1 < NN) ? cwp[r1] : 0.f;
    }
    #pragma unroll
    for (int j = 0; j < 4; j++) {
        int ncol = wn * 32 + j * 8 + 2 * tg;
        int n0 = n_block + ncol;
        float b0 = bias[n0], b1 = bias[n0 + 1];
        float cs0 = 0.f, cs1 = 0.f, ws0 = 0.f, ws1 = 0.f;
        #pragma unroll
        for (int i = 0; i < 4; i++) {
            int r0 = m_block + wm * 64 + i * 16 + g;
            int r1 = r0 + 8;
            if (r0 < NN) {
                float v0 = fmaxf(acc[i][j][0] + b0, 0.f);
                float v1 = fmaxf(acc[i][j][1] + b1, 0.f);
                cs0 += v0; cs1 += v1;
                ws0 += cw0[i] * v0; ws1 += cw0[i] * v1;
            }
            if (r1 < NN) {
                float v2 = fmaxf(acc[i][j][2] + b0, 0.f);
                float v3 = fmaxf(acc[i][j][3] + b1, 0.f);
                cs0 += v2; cs1 += v3;
                ws0 += cw1[i] * v2; ws1 += cw1[i] * v3;
            }
        }
        atomicAdd(&scol[ncol], cs0);
        atomicAdd(&scol[ncol + 1], cs1);
        atomicAdd(&scol2[ncol], ws0);
        atomicAdd(&scol2[ncol + 1], ws1);
    }
    __syncthreads();
    if (tid < 128) {
        atomicAdd(&g_colsum[gi * DD + n_block + tid], scol[tid]);
        atomicAdd(&g_s2[gi * DD + n_block + tid], scol2[tid]);
    }
}

// ---------------- h rows needed by emb2 (graph 0): var's in-neighbors + var -
// Agg from fp16 hi+lo pair, x and weights in fp32.
__global__ void var_h_kernel(const int* __restrict__ varp, const float* __restrict__ x,
                             const float* __restrict__ Wl, const float* __restrict__ Wr,
                             const float* __restrict__ bias) {
    int var = *varp;
    int p0 = g_start[var], p1 = g_start[var + 1];
    float inv = g_inv[var];
    int w = threadIdx.x >> 5, lane = threadIdx.x & 31;
    bool isvar = (blockIdx.x == 96);
    for (int p = p0 + blockIdx.x; isvar || p < p1; p += 96) {
        int row = isvar ? var : g_sorted[p];
        size_t base = (size_t)row * DD;
        for (int j = w; j < DD; j += 8) {
            const float* wl = Wl + (size_t)j * DD;
            const float* wr = Wr + (size_t)j * DD;
            float acc = 0.f;
            for (int k = lane; k < DD; k += 32) {
                float av = h2f(g_ah[base + k]) + h2f(g_al[base + k]);
                acc += av * wl[k] + x[base + k] * wr[k];
            }
            #pragma unroll
            for (int o = 16; o; o >>= 1) acc += __shfl_xor_sync(0xffffffffu, acc, o);
            if (lane == 0) {
                float hv = fmaxf(acc + bias[j], 0.f);
                if (isvar) g_rowvar[j] = hv;
                else atomicAdd(&g_agg2var[j], hv * inv);
            }
        }
        if (isvar) break;
    }
}

// ---------------- layer-2 matvecs: all 3 in one launch (grid 768 x 3) ------
__global__ void matvec2_kernel(const float* __restrict__ Wl, const float* __restrict__ bias,
                               const float* __restrict__ Wr) {
    int mode = blockIdx.y;
    const float *a, *b; float s; float* out;
    if (mode == 0)      { a = g_s2;      b = g_colsum;      s = 1.0f / NN; out = g_emb1; }
    else if (mode == 1) { a = g_agg2var; b = g_rowvar;      s = 1.0f;      out = g_emb2; }
    else                { a = g_s2 + DD; b = g_colsum + DD; s = 1.0f / NN; out = g_embt; }
    int j = blockIdx.x, t = threadIdx.x;   // 128 threads
    const float* wl = Wl + (size_t)j * DD;
    const float* wr = Wr + (size_t)j * DD;
    float p = 0.f;
    for (int k = t; k < DD; k += 128) p += a[k] * wl[k] + b[k] * wr[k];
    #pragma unroll
    for (int o = 16; o; o >>= 1) p += __shfl_xor_sync(0xffffffffu, p, o);
    __shared__ float sw[4];
    if ((t & 31) == 0) sw[t >> 5] = p;
    __syncthreads();
    if (t == 0) out[j] = (sw[0] + sw[1] + sw[2] + sw[3]) * s + bias[j];
}

// ---------------- head (feats computed inline from emb1/emb2) ----------------
__global__ void out_kernel(const float* __restrict__ linW, const float* __restrict__ linb,
                           const float* __restrict__ Wo, const float* __restrict__ ov,
                           const int* __restrict__ opp, float* __restrict__ dout) {
    int j = blockIdx.x, t = threadIdx.x;   // 256 threads
    const float* w = linW + (size_t)j * (3 * DD);
    float p = 0.f;
    for (int k = t; k < 3 * DD; k += 256) {
        float f;
        if (k < DD)           f = g_emb1[k];
        else if (k < 2 * DD)  f = g_emb2[k - DD];
        else                  f = g_emb1[k - 2 * DD] * g_emb2[k - 2 * DD];
        p += w[k] * f;
    }
    #pragma unroll
    for (int o = 16; o; o >>= 1) p += __shfl_xor_sync(0xffffffffu, p, o);
    __shared__ float sw[8];
    if ((t & 31) == 0) sw[t >> 5] = p;
    __syncthreads();
    if (t == 0) {
        float tot = 0.f;
        #pragma unroll
        for (int i = 0; i < 8; i++) tot += sw[i];
        int op = *opp - 1;
        float o = (tot + linb[j]) * Wo[(size_t)op * DD + j];
        float tg = g_embt[j] + ov[(size_t)op * DD + j];
        g_outv[j] = o; g_tgt[j] = tg;
        dout[3 + j] = o;
    }
}

__global__ void final_kernel(const float* __restrict__ labels, float* __restrict__ dout) {
    int t = threadIdx.x;   // 256
    float dd = 0.f, no = 0.f, nt = 0.f;
    for (int j = t; j < DD; j += 256) {
        float o = g_outv[j], g = g_tgt[j];
        dd += o * g; no += o * o; nt += g * g;
    }
    #pragma unroll
    for (int o = 16; o; o >>= 1) {
        dd += __shfl_xor_sync(0xffffffffu, dd, o);
        no += __shfl_xor_sync(0xffffffffu, no, o);
        nt += __shfl_xor_sync(0xffffffffu, nt, o);
    }
    __shared__ float s0[8], s1[8], s2[8];
    if ((t & 31) == 0) { s0[t >> 5] = dd; s1[t >> 5] = no; s2[t >> 5] = nt; }
    __syncthreads();
    if (t == 0) {
        float D_ = 0.f, NO = 0.f, NT = 0.f;
        #pragma unroll
        for (int i = 0; i < 8; i++) { D_ += s0[i]; NO += s1[i]; NT += s2[i]; }
        float n1 = fmaxf(sqrtf(NO), 1e-8f);
        float n2 = fmaxf(sqrtf(NT), 1e-8f);
        float score = D_ / (n1 * n2);
        float lab = labels[0];
        float loss = (score - lab) * (score - lab);
        dout[0] = loss; dout[1] = score; dout[2] = lab;
    }
}

// ---------------- launch ----------------
extern "C" void kernel_launch(void* const* d_in, const int* in_sizes, int n_in,
                              void* d_out, int out_size) {
    (void)in_sizes; (void)n_in; (void)out_size;
    const float* x1   = (const float*)d_in[0];
    const int*   ei1  = (const int*)d_in[1];
    const int*   varp = (const int*)d_in[2];
    const float* xt   = (const float*)d_in[3];
    const int*   eit  = (const int*)d_in[4];
    const int*   opp  = (const int*)d_in[5];
    const float* labels = (const float*)d_in[6];
    const float* Wl1 = (const float*)d_in[7];
    const float* bl1 = (const float*)d_in[8];
    const float* Wr1 = (const float*)d_in[9];
    const float* Wl2 = (const float*)d_in[10];
    const float* bl2 = (const float*)d_in[11];
    const float* Wr2 = (const float*)d_in[12];
    const float* linW = (const float*)d_in[13];
    const float* linb = (const float*)d_in[14];
    const float* Wo  = (const float*)d_in[15];
    const float* ov  = (const float*)d_in[16];
    float* dout = (float*)d_out;

    static bool attr_set = false;
    if (!attr_set) {
        cudaFuncSetAttribute(gemm_mma_kernel,
                             cudaFuncAttributeMaxDynamicSharedMemorySize, SMEM_GEMM);
        attr_set = true;
    }

    const int EB = (NE + 255) / 256;
    const int XB = (int)((NND / 8 + 255) / 256);

    convert_b_kernel<<<(DD * K2 + 255) / 256, 256>>>(Wl1, Wr1);
    zero_graph_kernel<<<(2 * NN + 255) / 256, 256>>>();
    count_kernel<<<dim3(EB, 2), 256>>>(ei1, eit);
    prefix_kernel<<<2, 1024>>>();
    place_kernel<<<dim3(EB, 2), 256>>>(ei1, eit);
    convert_x_kernel<<<dim3(XB, 2), 256>>>(x1, xt);
    gather_agg_kernel<<<dim3(3750, 3, 2), 256>>>();
    var_h_kernel<<<97, 256>>>(varp, x1, Wl1, Wr1, bl1);
    gemm_mma_kernel<<<dim3(6, 235, 2), 256, SMEM_GEMM>>>(bl1);
    matvec2_kernel<<<dim3(768, 3), 128>>>(Wl2, bl2, Wr2);
    out_kernel<<<768, 256>>>(linW, linb, Wo, ov, opp, dout);
    final_kernel<<<1, 256>>>(labels, dout);
}